// round 13
// baseline (speedup 1.0000x reference)
#include <cuda_runtime.h>
#include <math.h>
#include <stdint.h>

// ---------------- problem constants ----------------
#define B_   2
#define T_   1024
#define C_   768
#define H_   12
#define D_   64
#define L_   12
#define FF_  3072
#define V_   50257
#define VP_  50304          // 393 * 128
#define BT_  (B_ * T_)      // 2048
#define C3_  (3 * C_)       // 2304

// ---------------- device scratch ----------------
__device__ float g_x  [BT_ * C_];
__device__ float g_h  [BT_ * C_];
__device__ float g_qkv[BT_ * C3_];
__device__ float g_y  [BT_ * C_];
__device__ float g_ff [BT_ * FF_];
__device__ float g_Wp [C_ * VP_];            // padded + tf32-rounded Whead
__device__ float g_Wqkv_t[L_ * C_ * C3_];    // tf32-rounded weights
__device__ float g_Wo_t  [L_ * C_ * C_];
__device__ float g_Wfc_t [L_ * C_ * FF_];
__device__ float g_Wpr_t [L_ * FF_ * C_];
__device__ int   g_idx_is64;

// sizes (in float4 units) for the merged rounding kernel
#define N4_QKV (L_ * C_ * C3_ / 4)
#define N4_WO  (L_ * C_ * C_ / 4)
#define N4_FC  (L_ * C_ * FF_ / 4)
#define N4_PR  (L_ * FF_ * C_ / 4)
#define N4_ALL (N4_QKV + N4_WO + N4_FC + N4_PR)

// ---------------- tf32 helper ----------------
__device__ __forceinline__ uint32_t tf32_of(float x) {
    uint32_t u;
    asm("cvt.rna.tf32.f32 %0, %1;" : "=r"(u) : "f"(x));
    return u;
}
__device__ __forceinline__ float tf32_round(float x) {
    return __uint_as_float(tf32_of(x));
}

// ---------------- idx dtype detection ----------------
__global__ void detect_idx_kernel(const int* w) {
    __shared__ int found;
    if (threadIdx.x == 0) found = 0;
    __syncthreads();
    for (int i = threadIdx.x; i < BT_ / 2; i += blockDim.x)
        if (w[2 * i + 1] != 0) found = 1;
    __syncthreads();
    if (threadIdx.x == 0) g_idx_is64 = found ? 0 : 1;
}

// ---------------- embedding ----------------
__global__ void embed_kernel(const int* idxw, const float* tok, const float* pos,
                             float* x) {
    int i = blockIdx.x * blockDim.x + threadIdx.x;
    if (i >= BT_ * C_) return;
    int bt = i / C_;
    int c  = i - bt * C_;
    int t  = bt % T_;
    int token = g_idx_is64 ? idxw[2 * bt] : idxw[bt];
    x[i] = tok[(size_t)token * C_ + c] + pos[t * C_ + c];
}

// ---------------- merged tf32 pre-round for all four weight groups ----------------
__global__ void round_all_kernel(const float* __restrict__ Wqkv,
                                 const float* __restrict__ Wo,
                                 const float* __restrict__ Wfc,
                                 const float* __restrict__ Wpr,
                                 float* __restrict__ Dqkv,
                                 float* __restrict__ Do_,
                                 float* __restrict__ Dfc,
                                 float* __restrict__ Dpr) {
    int i = blockIdx.x * blockDim.x + threadIdx.x;
    if (i >= N4_ALL) return;
    const float4* src;
    float4* dst;
    int j = i;
    if (j < N4_QKV) {
        src = reinterpret_cast<const float4*>(Wqkv);
        dst = reinterpret_cast<float4*>(Dqkv);
    } else if ((j -= N4_QKV) < N4_WO) {
        src = reinterpret_cast<const float4*>(Wo);
        dst = reinterpret_cast<float4*>(Do_);
    } else if ((j -= N4_WO) < N4_FC) {
        src = reinterpret_cast<const float4*>(Wfc);
        dst = reinterpret_cast<float4*>(Dfc);
    } else {
        j -= N4_FC;
        src = reinterpret_cast<const float4*>(Wpr);
        dst = reinterpret_cast<float4*>(Dpr);
    }
    float4 v = src[j];
    v.x = tf32_round(v.x); v.y = tf32_round(v.y);
    v.z = tf32_round(v.z); v.w = tf32_round(v.w);
    dst[j] = v;
}

// ---------------- pad + round Whead to stride VP_ ----------------
__global__ void padW_kernel(const float* __restrict__ W, float* __restrict__ Wp) {
    int i = blockIdx.x * blockDim.x + threadIdx.x;
    if (i >= C_ * VP_) return;
    int row = i / VP_;
    int col = i - row * VP_;
    Wp[i] = (col < V_) ? tf32_round(W[(size_t)row * V_ + col]) : 0.f;
}

// ---------------- layernorm: one warp per row, 8 rows per CTA ----------------
// Output feeds GEMM A-side only -> emit tf32-rounded values.
__global__ __launch_bounds__(256)
void ln_kernel(const float* __restrict__ x, float* __restrict__ out,
               const float* __restrict__ s, const float* __restrict__ b) {
    int warp = threadIdx.x >> 5;
    int lane = threadIdx.x & 31;
    int row  = blockIdx.x * 8 + warp;
    const float* xr = x + (size_t)row * C_;
    float4 v[6];
    float sum = 0.f, sq = 0.f;
#pragma unroll
    for (int i = 0; i < 6; i++) {
        v[i] = *reinterpret_cast<const float4*>(&xr[(i * 32 + lane) * 4]);
        sum += v[i].x + v[i].y + v[i].z + v[i].w;
        sq  += v[i].x * v[i].x + v[i].y * v[i].y
             + v[i].z * v[i].z + v[i].w * v[i].w;
    }
#pragma unroll
    for (int off = 16; off > 0; off >>= 1) {
        sum += __shfl_xor_sync(0xffffffffu, sum, off);
        sq  += __shfl_xor_sync(0xffffffffu, sq,  off);
    }
    float mu  = sum * (1.f / C_);
    float var = sq * (1.f / C_) - mu * mu;
    float inv = rsqrtf(var + 1e-5f);
    float* orow = out + (size_t)row * C_;
#pragma unroll
    for (int i = 0; i < 6; i++) {
        int c = (i * 32 + lane) * 4;
        float4 sv = *reinterpret_cast<const float4*>(&s[c]);
        float4 bv = *reinterpret_cast<const float4*>(&b[c]);
        float4 o;
        o.x = tf32_round((v[i].x - mu) * inv * sv.x + bv.x);
        o.y = tf32_round((v[i].y - mu) * inv * sv.y + bv.y);
        o.z = tf32_round((v[i].z - mu) * inv * sv.z + bv.z);
        o.w = tf32_round((v[i].w - mu) * inv * sv.w + bv.w);
        *reinterpret_cast<float4*>(&orow[c]) = o;
    }
}

// ---------------- cp.async helpers ----------------
__device__ __forceinline__ uint32_t smem_u32(const void* p) {
    return (uint32_t)__cvta_generic_to_shared(p);
}
__device__ __forceinline__ void cp16(uint32_t dst, const void* src) {
    asm volatile("cp.async.ca.shared.global [%0], [%1], 16;" :: "r"(dst), "l"(src));
}
__device__ __forceinline__ void cp_commit() {
    asm volatile("cp.async.commit_group;");
}
template <int Ngrp>
__device__ __forceinline__ void cp_wait() {
    asm volatile("cp.async.wait_group %0;" :: "n"(Ngrp));
}

__device__ __forceinline__ void mma_tf32(float* c, const uint32_t* a, const uint32_t* b) {
    asm volatile(
        "mma.sync.aligned.m16n8k8.row.col.f32.tf32.tf32.f32 "
        "{%0,%1,%2,%3}, {%4,%5,%6,%7}, {%8,%9}, {%0,%1,%2,%3};"
        : "+f"(c[0]), "+f"(c[1]), "+f"(c[2]), "+f"(c[3])
        : "r"(a[0]), "r"(a[1]), "r"(a[2]), "r"(a[3]), "r"(b[0]), "r"(b[1]));
}

// ---------------- tf32 GEMM: 128x128, BK=16, FIVE-stage cp.async -----------------
// Identical to the 7,324us kernel except pipeline depth 3 -> 5 (prefetch distance
// 2 -> 4 iterations) to cover DRAM latency on the B stream. 1 sync/iter unchanged.
// Inputs MUST be pre-rounded to tf32 bit patterns. No cvt in mainloop.
#define GBM 128
#define GBN 128
#define GBK 16
#define ALD 20
#define BLD 136
#define A_ST (GBM * ALD)
#define B_ST (GBK * BLD)
#define STAGES 5
#define GEMM_SMEM (STAGES * (A_ST + B_ST) * 4)   // 94720 B

__global__ __launch_bounds__(256)
void tgemm_kernel(const float* __restrict__ A, const float* __restrict__ W,
                  const float* __restrict__ bias, const float* __restrict__ Res,
                  float* __restrict__ Cout, int M, int Nout, int K, int ldw,
                  int act, int rnd) {
    extern __shared__ float smg[];
    float* sA = smg;
    float* sB = smg + STAGES * A_ST;

    int bn = blockIdx.x * GBN;
    int bm = blockIdx.y * GBM;
    int tid  = threadIdx.x;
    int lane = tid & 31;
    int warp = tid >> 5;
    int wm = warp >> 2;
    int wn = warp & 3;
    int g   = lane >> 2;
    int tig = lane & 3;

    int a_r  = tid >> 2;
    int a_f4 = (tid & 3) * 4;
    int b_r  = tid >> 5;
    int b_c4 = (tid & 31) * 4;

    auto load_tiles = [&](int s, int k0) {
        float* As = sA + s * A_ST;
        float* Bs = sB + s * B_ST;
#pragma unroll
        for (int it = 0; it < 2; it++) {
            int row = a_r + it * 64;
            cp16(smem_u32(&As[row * ALD + a_f4]),
                 &A[(size_t)(bm + row) * K + k0 + a_f4]);
        }
#pragma unroll
        for (int it = 0; it < 2; it++) {
            int kr = b_r + it * 8;
            cp16(smem_u32(&Bs[kr * BLD + b_c4]),
                 &W[(size_t)(k0 + kr) * ldw + bn + b_c4]);
        }
    };

    float acc[4][4][4];
#pragma unroll
    for (int mi = 0; mi < 4; mi++)
#pragma unroll
        for (int ni = 0; ni < 4; ni++)
#pragma unroll
            for (int e = 0; e < 4; e++) acc[mi][ni][e] = 0.f;

    int KT = K / GBK;
    // prologue: fill up to STAGES-1 tiles
#pragma unroll
    for (int s = 0; s < STAGES - 1; s++) {
        if (s < KT) { load_tiles(s, s * GBK); cp_commit(); }
    }

    for (int kt = 0; kt < KT; kt++) {
        int rem = KT - 1 - kt;   // future tiles already committed beyond kt
        if (rem >= 3)      cp_wait<3>();
        else if (rem == 2) cp_wait<2>();
        else if (rem == 1) cp_wait<1>();
        else               cp_wait<0>();
        __syncthreads();
        if (kt + STAGES - 1 < KT) {
            load_tiles((kt + STAGES - 1) % STAGES, (kt + STAGES - 1) * GBK);
            cp_commit();
        }

        const uint32_t* As = reinterpret_cast<const uint32_t*>(sA + (kt % STAGES) * A_ST);
        const uint32_t* Bs = reinterpret_cast<const uint32_t*>(sB + (kt % STAGES) * B_ST);
#pragma unroll
        for (int ks = 0; ks < 2; ks++) {
            int kb = ks * 8;
            uint32_t af[4][4], bf[4][2];
#pragma unroll
            for (int mi = 0; mi < 4; mi++) {
                int m0 = wm * 64 + mi * 16;
                af[mi][0] = As[(m0 + g    ) * ALD + kb + tig    ];
                af[mi][1] = As[(m0 + g + 8) * ALD + kb + tig    ];
                af[mi][2] = As[(m0 + g    ) * ALD + kb + tig + 4];
                af[mi][3] = As[(m0 + g + 8) * ALD + kb + tig + 4];
            }
#pragma unroll
            for (int ni = 0; ni < 4; ni++) {
                int n0 = wn * 32 + ni * 8;
                bf[ni][0] = Bs[(kb + tig    ) * BLD + n0 + g];
                bf[ni][1] = Bs[(kb + tig + 4) * BLD + n0 + g];
            }
#pragma unroll
            for (int mi = 0; mi < 4; mi++)
#pragma unroll
                for (int ni = 0; ni < 4; ni++)
                    mma_tf32(acc[mi][ni], af[mi], bf[ni]);
        }
    }
    __syncthreads();

    bool evenN = ((Nout & 1) == 0);
#pragma unroll
    for (int mi = 0; mi < 4; mi++) {
        int r0 = bm + wm * 64 + mi * 16 + g;
#pragma unroll
        for (int ni = 0; ni < 4; ni++) {
            int col0 = bn + wn * 32 + ni * 8 + 2 * tig;
#pragma unroll
            for (int ep = 0; ep < 4; ep += 2) {
                int row = r0 + (ep >> 1) * 8;
                float v0 = acc[mi][ni][ep];
                float v1 = acc[mi][ni][ep + 1];
                if (bias) { v0 += bias[col0]; v1 += bias[col0 + 1]; }
                if (act == 1) {
                    v0 = 0.5f * v0 * (1.f + erff(v0 * 0.70710678118654752f));
                    v1 = 0.5f * v1 * (1.f + erff(v1 * 0.70710678118654752f));
                }
                if (rnd) { v0 = tf32_round(v0); v1 = tf32_round(v1); }
                size_t o = (size_t)row * Nout + col0;
                if (evenN) {
                    if (Res) { v0 += Res[o]; v1 += Res[o + 1]; }
                    float2 st = {v0, v1};
                    *reinterpret_cast<float2*>(&Cout[o]) = st;
                } else {
                    if (col0 < Nout) {
                        if (Res) v0 += Res[o];
                        Cout[o] = v0;
                    }
                    if (col0 + 1 < Nout) {
                        if (Res) v1 += Res[o + 1];
                        Cout[o + 1] = v1;
                    }
                }
            }
        }
    }
}

// ---------------- flash attention: one CTA per (b, h, 64-q tile) ----------------
// Output y feeds Wo GEMM A-side only -> emit tf32-rounded values.
#define ATT_SMEM ((3 * 64 * 64 + 64 * 65 + 128) * 4)

__global__ __launch_bounds__(256)
void attn_flash_kernel(const float* __restrict__ qkv, float* __restrict__ y) {
    extern __shared__ float sm[];
    float* Qs   = sm;
    float* Ks   = Qs + 64 * 64;
    float* Vs   = Ks + 64 * 64;
    float* Ps   = Vs + 64 * 64;
    float* mrow = Ps + 64 * 65;
    float* lrow = mrow + 64;

    int qt  = blockIdx.x;
    int h   = blockIdx.y;
    int b   = blockIdx.z;
    int tid = threadIdx.x;
    int tx  = tid & 15;
    int ty  = tid >> 4;
    const float scale = 0.125f;
    const float* base = qkv + (size_t)b * T_ * C3_;

    {
        int r  = tid >> 2;
        int d0 = (tid & 3) * 16;
        const float* qp = base + (size_t)(qt * 64 + r) * C3_ + h * 64 + d0;
#pragma unroll
        for (int i = 0; i < 4; i++) {
            float4 v = *reinterpret_cast<const float4*>(&qp[4 * i]);
            Qs[(d0 + 4 * i + 0) * 64 + r] = v.x;
            Qs[(d0 + 4 * i + 1) * 64 + r] = v.y;
            Qs[(d0 + 4 * i + 2) * 64 + r] = v.z;
            Qs[(d0 + 4 * i + 3) * 64 + r] = v.w;
        }
    }
    if (tid < 64) { mrow[tid] = -1e30f; lrow[tid] = 0.f; }

    float o[4][4];
#pragma unroll
    for (int i = 0; i < 4; i++)
#pragma unroll
        for (int j = 0; j < 4; j++) o[i][j] = 0.f;
    __syncthreads();

    for (int kt = 0; kt <= qt; kt++) {
        {
            int r  = tid >> 2;
            int d0 = (tid & 3) * 16;
            const float* kp = base + (size_t)(kt * 64 + r) * C3_ + C_ + h * 64 + d0;
            const float* vp = kp + C_;
#pragma unroll
            for (int i = 0; i < 4; i++) {
                float4 v = *reinterpret_cast<const float4*>(&kp[4 * i]);
                Ks[(d0 + 4 * i + 0) * 64 + r] = v.x;
                Ks[(d0 + 4 * i + 1) * 64 + r] = v.y;
                Ks[(d0 + 4 * i + 2) * 64 + r] = v.z;
                Ks[(d0 + 4 * i + 3) * 64 + r] = v.w;
            }
#pragma unroll
            for (int i = 0; i < 4; i++) {
                float4 v = *reinterpret_cast<const float4*>(&vp[4 * i]);
                *reinterpret_cast<float4*>(&Vs[r * 64 + d0 + 4 * i]) = v;
            }
        }
        __syncthreads();

        float cS[4][4];
#pragma unroll
        for (int i = 0; i < 4; i++)
#pragma unroll
            for (int j = 0; j < 4; j++) cS[i][j] = 0.f;
        for (int d = 0; d < 64; d++) {
            float4 aq = *reinterpret_cast<const float4*>(&Qs[d * 64 + 4 * ty]);
            float4 bk = *reinterpret_cast<const float4*>(&Ks[d * 64 + 4 * tx]);
            float a[4] = {aq.x, aq.y, aq.z, aq.w};
            float bb[4] = {bk.x, bk.y, bk.z, bk.w};
#pragma unroll
            for (int i = 0; i < 4; i++)
#pragma unroll
                for (int j = 0; j < 4; j++) cS[i][j] += a[i] * bb[j];
        }

        float al[4];
        bool diag = (kt == qt);
#pragma unroll
        for (int i = 0; i < 4; i++) {
            int r  = 4 * ty + i;
            int qg = qt * 64 + r;
            float rmax = -1e30f;
#pragma unroll
            for (int j = 0; j < 4; j++) {
                float s = cS[i][j] * scale;
                if (diag && (kt * 64 + 4 * tx + j) > qg) s = -1e30f;
                cS[i][j] = s;
                rmax = fmaxf(rmax, s);
            }
#pragma unroll
            for (int off = 8; off > 0; off >>= 1)
                rmax = fmaxf(rmax, __shfl_xor_sync(0xffffffffu, rmax, off));
            float mo = mrow[r];
            float mn = fmaxf(mo, rmax);
            float sum = 0.f;
#pragma unroll
            for (int j = 0; j < 4; j++) {
                float p = __expf(cS[i][j] - mn);
                cS[i][j] = p;
                sum += p;
            }
#pragma unroll
            for (int off = 8; off > 0; off >>= 1)
                sum += __shfl_xor_sync(0xffffffffu, sum, off);
            al[i] = __expf(mo - mn);
            if (tx == 0) {
                mrow[r] = mn;
                lrow[r] = lrow[r] * al[i] + sum;
            }
        }
#pragma unroll
        for (int i = 0; i < 4; i++) {
#pragma unroll
            for (int j = 0; j < 4; j++) {
                o[i][j] *= al[i];
                Ps[(4 * ty + i) * 65 + 4 * tx + j] = cS[i][j];
            }
        }
        __syncthreads();

        for (int k = 0; k < 64; k++) {
            float a0 = Ps[(4 * ty + 0) * 65 + k];
            float a1 = Ps[(4 * ty + 1) * 65 + k];
            float a2 = Ps[(4 * ty + 2) * 65 + k];
            float a3 = Ps[(4 * ty + 3) * 65 + k];
            float4 bv = *reinterpret_cast<const float4*>(&Vs[k * 64 + 4 * tx]);
            float bb[4] = {bv.x, bv.y, bv.z, bv.w};
#pragma unroll
            for (int j = 0; j < 4; j++) {
                o[0][j] += a0 * bb[j];
                o[1][j] += a1 * bb[j];
                o[2][j] += a2 * bb[j];
                o[3][j] += a3 * bb[j];
            }
        }
        __syncthreads();
    }

#pragma unroll
    for (int i = 0; i < 4; i++) {
        int r = 4 * ty + i;
        float linv = 1.f / lrow[r];
        size_t row = (size_t)(b * T_ + qt * 64 + r) * C_ + h * 64 + 4 * tx;
        float4 v;
        v.x = tf32_round(o[i][0] * linv); v.y = tf32_round(o[i][1] * linv);
        v.z = tf32_round(o[i][2] * linv); v.w = tf32_round(o[i][3] * linv);
        *reinterpret_cast<float4*>(&y[row]) = v;
    }
}

// ---------------- host launcher ----------------
extern "C" void kernel_launch(void* const* d_in, const int* in_sizes, int n_in,
                              void* d_out, int out_size) {
    const int*   idxw    = (const int*)  d_in[0];
    const float* tok_emb = (const float*)d_in[1];
    const float* pos_emb = (const float*)d_in[2];
    const float* ln1_s   = (const float*)d_in[3];
    const float* ln1_b   = (const float*)d_in[4];
    const float* Wqkv    = (const float*)d_in[5];
    const float* bqkv    = (const float*)d_in[6];
    const float* Wo      = (const float*)d_in[7];
    const float* bo      = (const float*)d_in[8];
    const float* ln2_s   = (const float*)d_in[9];
    const float* ln2_b   = (const float*)d_in[10];
    const float* Wfc     = (const float*)d_in[11];
    const float* bfc     = (const float*)d_in[12];
    const float* Wpr     = (const float*)d_in[13];
    const float* bpr     = (const float*)d_in[14];
    const float* lnf_s   = (const float*)d_in[15];
    const float* lnf_b   = (const float*)d_in[16];
    const float* Whead   = (const float*)d_in[17];
    float* out = (float*)d_out;

    float *x, *h, *qkv, *y, *ff, *Wp, *Wqkv_t, *Wo_t, *Wfc_t, *Wpr_t;
    cudaGetSymbolAddress((void**)&x,      g_x);
    cudaGetSymbolAddress((void**)&h,      g_h);
    cudaGetSymbolAddress((void**)&qkv,    g_qkv);
    cudaGetSymbolAddress((void**)&y,      g_y);
    cudaGetSymbolAddress((void**)&ff,     g_ff);
    cudaGetSymbolAddress((void**)&Wp,     g_Wp);
    cudaGetSymbolAddress((void**)&Wqkv_t, g_Wqkv_t);
    cudaGetSymbolAddress((void**)&Wo_t,   g_Wo_t);
    cudaGetSymbolAddress((void**)&Wfc_t,  g_Wfc_t);
    cudaGetSymbolAddress((void**)&Wpr_t,  g_Wpr_t);

    cudaFuncSetAttribute(attn_flash_kernel,
                         cudaFuncAttributeMaxDynamicSharedMemorySize, ATT_SMEM);
    cudaFuncSetAttribute(tgemm_kernel,
                         cudaFuncAttributeMaxDynamicSharedMemorySize, GEMM_SMEM);

    detect_idx_kernel<<<1, 256>>>(idxw);
    embed_kernel<<<(BT_ * C_ + 255) / 256, 256>>>(idxw, tok_emb, pos_emb, x);
    padW_kernel<<<(C_ * VP_ + 255) / 256, 256>>>(Whead, Wp);
    round_all_kernel<<<(N4_ALL + 255) / 256, 256>>>(Wqkv, Wo, Wfc, Wpr,
                                                    Wqkv_t, Wo_t, Wfc_t, Wpr_t);

    dim3 gQKV(C3_ / GBN, BT_ / GBM);
    dim3 gPROJ(C_ / GBN, BT_ / GBM);
    dim3 gFC(FF_ / GBN, BT_ / GBM);
    dim3 gHEAD(VP_ / GBN, BT_ / GBM);
    dim3 gATT(T_ / 64, H_, B_);

    for (int l = 0; l < L_; l++) {
        ln_kernel<<<BT_ / 8, 256>>>(x, h, ln1_s + (size_t)l * C_, ln1_b + (size_t)l * C_);
        tgemm_kernel<<<gQKV, 256, GEMM_SMEM>>>(h, Wqkv_t + (size_t)l * C_ * C3_,
                                    bqkv + (size_t)l * C3_, nullptr, qkv,
                                    BT_, C3_, C_, C3_, 0, 0);
        attn_flash_kernel<<<gATT, 256, ATT_SMEM>>>(qkv, y);
        tgemm_kernel<<<gPROJ, 256, GEMM_SMEM>>>(y, Wo_t + (size_t)l * C_ * C_,
                                     bo + (size_t)l * C_, x, x,
                                     BT_, C_, C_, C_, 0, 0);
        ln_kernel<<<BT_ / 8, 256>>>(x, h, ln2_s + (size_t)l * C_, ln2_b + (size_t)l * C_);
        tgemm_kernel<<<gFC, 256, GEMM_SMEM>>>(h, Wfc_t + (size_t)l * C_ * FF_,
                                   bfc + (size_t)l * FF_, nullptr, ff,
                                   BT_, FF_, C_, FF_, 1, 1);
        tgemm_kernel<<<gPROJ, 256, GEMM_SMEM>>>(ff, Wpr_t + (size_t)l * FF_ * C_,
                                     bpr + (size_t)l * C_, x, x,
                                     BT_, C_, FF_, C_, 0, 0);
    }

    ln_kernel<<<BT_ / 8, 256>>>(x, h, lnf_s, lnf_b);
    tgemm_kernel<<<gHEAD, 256, GEMM_SMEM>>>(h, Wp, nullptr, nullptr, out,
                                 BT_, V_, C_, VP_, 0, 0);
}

// round 14
// speedup vs baseline: 1.1145x; 1.1145x over previous
#include <cuda_runtime.h>
#include <math.h>
#include <stdint.h>

// ---------------- problem constants ----------------
#define B_   2
#define T_   1024
#define C_   768
#define H_   12
#define D_   64
#define L_   12
#define FF_  3072
#define V_   50257
#define VP_  50304          // 393 * 128
#define BT_  (B_ * T_)      // 2048
#define C3_  (3 * C_)       // 2304
#define SK_  3              // split-K factor for N=768 GEMMs

// ---------------- device scratch ----------------
__device__ float g_x  [BT_ * C_];
__device__ float g_h  [BT_ * C_];
__device__ float g_qkv[BT_ * C3_];
__device__ float g_y  [BT_ * C_];
__device__ float g_ff [BT_ * FF_];
__device__ float g_part[SK_ * BT_ * C_];     // split-K partials
__device__ float g_Wp [C_ * VP_];            // padded + tf32-rounded Whead
__device__ float g_Wqkv_t[L_ * C_ * C3_];    // tf32-rounded weights
__device__ float g_Wo_t  [L_ * C_ * C_];
__device__ float g_Wfc_t [L_ * C_ * FF_];
__device__ float g_Wpr_t [L_ * FF_ * C_];
__device__ int   g_idx_is64;

// sizes (in float4 units) for the merged rounding kernel
#define N4_QKV (L_ * C_ * C3_ / 4)
#define N4_WO  (L_ * C_ * C_ / 4)
#define N4_FC  (L_ * C_ * FF_ / 4)
#define N4_PR  (L_ * FF_ * C_ / 4)
#define N4_ALL (N4_QKV + N4_WO + N4_FC + N4_PR)

// ---------------- tf32 helper ----------------
__device__ __forceinline__ uint32_t tf32_of(float x) {
    uint32_t u;
    asm("cvt.rna.tf32.f32 %0, %1;" : "=r"(u) : "f"(x));
    return u;
}
__device__ __forceinline__ float tf32_round(float x) {
    return __uint_as_float(tf32_of(x));
}

// ---------------- idx dtype detection ----------------
__global__ void detect_idx_kernel(const int* w) {
    __shared__ int found;
    if (threadIdx.x == 0) found = 0;
    __syncthreads();
    for (int i = threadIdx.x; i < BT_ / 2; i += blockDim.x)
        if (w[2 * i + 1] != 0) found = 1;
    __syncthreads();
    if (threadIdx.x == 0) g_idx_is64 = found ? 0 : 1;
}

// ---------------- embedding ----------------
__global__ void embed_kernel(const int* idxw, const float* tok, const float* pos,
                             float* x) {
    int i = blockIdx.x * blockDim.x + threadIdx.x;
    if (i >= BT_ * C_) return;
    int bt = i / C_;
    int c  = i - bt * C_;
    int t  = bt % T_;
    int token = g_idx_is64 ? idxw[2 * bt] : idxw[bt];
    x[i] = tok[(size_t)token * C_ + c] + pos[t * C_ + c];
}

// ---------------- merged tf32 pre-round for all four weight groups ----------------
__global__ void round_all_kernel(const float* __restrict__ Wqkv,
                                 const float* __restrict__ Wo,
                                 const float* __restrict__ Wfc,
                                 const float* __restrict__ Wpr,
                                 float* __restrict__ Dqkv,
                                 float* __restrict__ Do_,
                                 float* __restrict__ Dfc,
                                 float* __restrict__ Dpr) {
    int i = blockIdx.x * blockDim.x + threadIdx.x;
    if (i >= N4_ALL) return;
    const float4* src;
    float4* dst;
    int j = i;
    if (j < N4_QKV) {
        src = reinterpret_cast<const float4*>(Wqkv);
        dst = reinterpret_cast<float4*>(Dqkv);
    } else if ((j -= N4_QKV) < N4_WO) {
        src = reinterpret_cast<const float4*>(Wo);
        dst = reinterpret_cast<float4*>(Do_);
    } else if ((j -= N4_WO) < N4_FC) {
        src = reinterpret_cast<const float4*>(Wfc);
        dst = reinterpret_cast<float4*>(Dfc);
    } else {
        j -= N4_FC;
        src = reinterpret_cast<const float4*>(Wpr);
        dst = reinterpret_cast<float4*>(Dpr);
    }
    float4 v = src[j];
    v.x = tf32_round(v.x); v.y = tf32_round(v.y);
    v.z = tf32_round(v.z); v.w = tf32_round(v.w);
    dst[j] = v;
}

// ---------------- pad + round Whead to stride VP_ ----------------
__global__ void padW_kernel(const float* __restrict__ W, float* __restrict__ Wp) {
    int i = blockIdx.x * blockDim.x + threadIdx.x;
    if (i >= C_ * VP_) return;
    int row = i / VP_;
    int col = i - row * VP_;
    Wp[i] = (col < V_) ? tf32_round(W[(size_t)row * V_ + col]) : 0.f;
}

// ---------------- split-K reduce: x += p0+p1+p2 + bias ----------------
__global__ void reduce_split_kernel(const float* __restrict__ part,
                                    const float* __restrict__ bias,
                                    float* __restrict__ x) {
    int i = blockIdx.x * blockDim.x + threadIdx.x;   // float4 index
    const int MN4 = BT_ * C_ / 4;
    if (i >= MN4) return;
    const float4* p = reinterpret_cast<const float4*>(part);
    float4 p0 = p[i];
    float4 p1 = p[i + MN4];
    float4 p2 = p[i + 2 * MN4];
    float4 xv = reinterpret_cast<const float4*>(x)[i];
    int col4 = (i * 4) % C_;
    float4 bv = *reinterpret_cast<const float4*>(&bias[col4]);
    float4 o;
    o.x = xv.x + p0.x + p1.x + p2.x + bv.x;
    o.y = xv.y + p0.y + p1.y + p2.y + bv.y;
    o.z = xv.z + p0.z + p1.z + p2.z + bv.z;
    o.w = xv.w + p0.w + p1.w + p2.w + bv.w;
    reinterpret_cast<float4*>(x)[i] = o;
}

// ---------------- layernorm: one warp per row, 8 rows per CTA ----------------
__global__ __launch_bounds__(256)
void ln_kernel(const float* __restrict__ x, float* __restrict__ out,
               const float* __restrict__ s, const float* __restrict__ b) {
    int warp = threadIdx.x >> 5;
    int lane = threadIdx.x & 31;
    int row  = blockIdx.x * 8 + warp;
    const float* xr = x + (size_t)row * C_;
    float4 v[6];
    float sum = 0.f, sq = 0.f;
#pragma unroll
    for (int i = 0; i < 6; i++) {
        v[i] = *reinterpret_cast<const float4*>(&xr[(i * 32 + lane) * 4]);
        sum += v[i].x + v[i].y + v[i].z + v[i].w;
        sq  += v[i].x * v[i].x + v[i].y * v[i].y
             + v[i].z * v[i].z + v[i].w * v[i].w;
    }
#pragma unroll
    for (int off = 16; off > 0; off >>= 1) {
        sum += __shfl_xor_sync(0xffffffffu, sum, off);
        sq  += __shfl_xor_sync(0xffffffffu, sq,  off);
    }
    float mu  = sum * (1.f / C_);
    float var = sq * (1.f / C_) - mu * mu;
    float inv = rsqrtf(var + 1e-5f);
    float* orow = out + (size_t)row * C_;
#pragma unroll
    for (int i = 0; i < 6; i++) {
        int c = (i * 32 + lane) * 4;
        float4 sv = *reinterpret_cast<const float4*>(&s[c]);
        float4 bv = *reinterpret_cast<const float4*>(&b[c]);
        float4 o;
        o.x = tf32_round((v[i].x - mu) * inv * sv.x + bv.x);
        o.y = tf32_round((v[i].y - mu) * inv * sv.y + bv.y);
        o.z = tf32_round((v[i].z - mu) * inv * sv.z + bv.z);
        o.w = tf32_round((v[i].w - mu) * inv * sv.w + bv.w);
        *reinterpret_cast<float4*>(&orow[c]) = o;
    }
}

// ---------------- cp.async helpers ----------------
__device__ __forceinline__ uint32_t smem_u32(const void* p) {
    return (uint32_t)__cvta_generic_to_shared(p);
}
__device__ __forceinline__ void cp16(uint32_t dst, const void* src) {
    asm volatile("cp.async.ca.shared.global [%0], [%1], 16;" :: "r"(dst), "l"(src));
}
__device__ __forceinline__ void cp_commit() {
    asm volatile("cp.async.commit_group;");
}
template <int Ngrp>
__device__ __forceinline__ void cp_wait() {
    asm volatile("cp.async.wait_group %0;" :: "n"(Ngrp));
}

__device__ __forceinline__ void mma_tf32(float* c, const uint32_t* a, const uint32_t* b) {
    asm volatile(
        "mma.sync.aligned.m16n8k8.row.col.f32.tf32.tf32.f32 "
        "{%0,%1,%2,%3}, {%4,%5,%6,%7}, {%8,%9}, {%0,%1,%2,%3};"
        : "+f"(c[0]), "+f"(c[1]), "+f"(c[2]), "+f"(c[3])
        : "r"(a[0]), "r"(a[1]), "r"(a[2]), "r"(a[3]), "r"(b[0]), "r"(b[1]));
}

// ---------------- tf32 GEMM: 128x128, BK=16, 3-stage cp.async (R12 verified) ------
// K = per-CTA K length; ldA = A row stride. blockIdx.z = split-K slice:
// slice z reads A cols [z*K, (z+1)*K) and W rows [z*K, (z+1)*K).
// gridDim.z > 1 => write raw partial accumulators to Cout + z*M*Nout.
#define GBM 128
#define GBN 128
#define GBK 16
#define ALD 20
#define BLD 136
#define A_ST (GBM * ALD)
#define B_ST (GBK * BLD)
#define GEMM_SMEM (3 * (A_ST + B_ST) * 4)

__global__ __launch_bounds__(256)
void tgemm_kernel(const float* __restrict__ A, const float* __restrict__ W,
                  const float* __restrict__ bias, const float* __restrict__ Res,
                  float* __restrict__ Cout, int M, int Nout, int K, int ldA,
                  int ldw, int act, int rnd) {
    extern __shared__ float smg[];
    float* sA = smg;
    float* sB = smg + 3 * A_ST;

    int z = blockIdx.z;
    const float* Ab = A + (size_t)z * K;          // advance along K
    const float* Wb = W + (size_t)z * K * ldw;    // advance along K rows

    int bn = blockIdx.x * GBN;
    int bm = blockIdx.y * GBM;
    int tid  = threadIdx.x;
    int lane = tid & 31;
    int warp = tid >> 5;
    int wm = warp >> 2;
    int wn = warp & 3;
    int g   = lane >> 2;
    int tig = lane & 3;

    int a_r  = tid >> 2;
    int a_f4 = (tid & 3) * 4;
    int b_r  = tid >> 5;
    int b_c4 = (tid & 31) * 4;

    auto load_tiles = [&](int s, int k0) {
        float* As = sA + s * A_ST;
        float* Bs = sB + s * B_ST;
#pragma unroll
        for (int it = 0; it < 2; it++) {
            int row = a_r + it * 64;
            cp16(smem_u32(&As[row * ALD + a_f4]),
                 &Ab[(size_t)(bm + row) * ldA + k0 + a_f4]);
        }
#pragma unroll
        for (int it = 0; it < 2; it++) {
            int kr = b_r + it * 8;
            cp16(smem_u32(&Bs[kr * BLD + b_c4]),
                 &Wb[(size_t)(k0 + kr) * ldw + bn + b_c4]);
        }
    };

    float acc[4][4][4];
#pragma unroll
    for (int mi = 0; mi < 4; mi++)
#pragma unroll
        for (int ni = 0; ni < 4; ni++)
#pragma unroll
            for (int e = 0; e < 4; e++) acc[mi][ni][e] = 0.f;

    int KT = K / GBK;
    load_tiles(0, 0);
    cp_commit();
    if (KT > 1) { load_tiles(1, GBK); cp_commit(); }

    for (int kt = 0; kt < KT; kt++) {
        if (kt + 1 < KT) cp_wait<1>(); else cp_wait<0>();
        __syncthreads();
        if (kt + 2 < KT) { load_tiles((kt + 2) % 3, (kt + 2) * GBK); cp_commit(); }

        const uint32_t* As = reinterpret_cast<const uint32_t*>(sA + (kt % 3) * A_ST);
        const uint32_t* Bs = reinterpret_cast<const uint32_t*>(sB + (kt % 3) * B_ST);
#pragma unroll
        for (int ks = 0; ks < 2; ks++) {
            int kb = ks * 8;
            uint32_t af[4][4], bf[4][2];
#pragma unroll
            for (int mi = 0; mi < 4; mi++) {
                int m0 = wm * 64 + mi * 16;
                af[mi][0] = As[(m0 + g    ) * ALD + kb + tig    ];
                af[mi][1] = As[(m0 + g + 8) * ALD + kb + tig    ];
                af[mi][2] = As[(m0 + g    ) * ALD + kb + tig + 4];
                af[mi][3] = As[(m0 + g + 8) * ALD + kb + tig + 4];
            }
#pragma unroll
            for (int ni = 0; ni < 4; ni++) {
                int n0 = wn * 32 + ni * 8;
                bf[ni][0] = Bs[(kb + tig    ) * BLD + n0 + g];
                bf[ni][1] = Bs[(kb + tig + 4) * BLD + n0 + g];
            }
#pragma unroll
            for (int mi = 0; mi < 4; mi++)
#pragma unroll
                for (int ni = 0; ni < 4; ni++)
                    mma_tf32(acc[mi][ni], af[mi], bf[ni]);
        }
    }
    __syncthreads();

    if (gridDim.z > 1) {
        // raw partial store (Nout even by construction)
        float* P = Cout + (size_t)z * M * Nout;
#pragma unroll
        for (int mi = 0; mi < 4; mi++) {
            int r0 = bm + wm * 64 + mi * 16 + g;
#pragma unroll
            for (int ni = 0; ni < 4; ni++) {
                int col0 = bn + wn * 32 + ni * 8 + 2 * tig;
#pragma unroll
                for (int ep = 0; ep < 4; ep += 2) {
                    int row = r0 + (ep >> 1) * 8;
                    float2 st = {acc[mi][ni][ep], acc[mi][ni][ep + 1]};
                    *reinterpret_cast<float2*>(&P[(size_t)row * Nout + col0]) = st;
                }
            }
        }
        return;
    }

    bool evenN = ((Nout & 1) == 0);
#pragma unroll
    for (int mi = 0; mi < 4; mi++) {
        int r0 = bm + wm * 64 + mi * 16 + g;
#pragma unroll
        for (int ni = 0; ni < 4; ni++) {
            int col0 = bn + wn * 32 + ni * 8 + 2 * tig;
#pragma unroll
            for (int ep = 0; ep < 4; ep += 2) {
                int row = r0 + (ep >> 1) * 8;
                float v0 = acc[mi][ni][ep];
                float v1 = acc[mi][ni][ep + 1];
                if (bias) { v0 += bias[col0]; v1 += bias[col0 + 1]; }
                if (act == 1) {
                    v0 = 0.5f * v0 * (1.f + erff(v0 * 0.70710678118654752f));
                    v1 = 0.5f * v1 * (1.f + erff(v1 * 0.70710678118654752f));
                }
                if (rnd) { v0 = tf32_round(v0); v1 = tf32_round(v1); }
                size_t o = (size_t)row * Nout + col0;
                if (evenN) {
                    if (Res) { v0 += Res[o]; v1 += Res[o + 1]; }
                    float2 st = {v0, v1};
                    *reinterpret_cast<float2*>(&Cout[o]) = st;
                } else {
                    if (col0 < Nout) {
                        if (Res) v0 += Res[o];
                        Cout[o] = v0;
                    }
                    if (col0 + 1 < Nout) {
                        if (Res) v1 += Res[o + 1];
                        Cout[o + 1] = v1;
                    }
                }
            }
        }
    }
}

// ---------------- flash attention: one CTA per (b, h, 64-q tile) ----------------
#define ATT_SMEM ((3 * 64 * 64 + 64 * 65 + 128) * 4)

__global__ __launch_bounds__(256)
void attn_flash_kernel(const float* __restrict__ qkv, float* __restrict__ y) {
    extern __shared__ float sm[];
    float* Qs   = sm;
    float* Ks   = Qs + 64 * 64;
    float* Vs   = Ks + 64 * 64;
    float* Ps   = Vs + 64 * 64;
    float* mrow = Ps + 64 * 65;
    float* lrow = mrow + 64;

    int qt  = blockIdx.x;
    int h   = blockIdx.y;
    int b   = blockIdx.z;
    int tid = threadIdx.x;
    int tx  = tid & 15;
    int ty  = tid >> 4;
    const float scale = 0.125f;
    const float* base = qkv + (size_t)b * T_ * C3_;

    {
        int r  = tid >> 2;
        int d0 = (tid & 3) * 16;
        const float* qp = base + (size_t)(qt * 64 + r) * C3_ + h * 64 + d0;
#pragma unroll
        for (int i = 0; i < 4; i++) {
            float4 v = *reinterpret_cast<const float4*>(&qp[4 * i]);
            Qs[(d0 + 4 * i + 0) * 64 + r] = v.x;
            Qs[(d0 + 4 * i + 1) * 64 + r] = v.y;
            Qs[(d0 + 4 * i + 2) * 64 + r] = v.z;
            Qs[(d0 + 4 * i + 3) * 64 + r] = v.w;
        }
    }
    if (tid < 64) { mrow[tid] = -1e30f; lrow[tid] = 0.f; }

    float o[4][4];
#pragma unroll
    for (int i = 0; i < 4; i++)
#pragma unroll
        for (int j = 0; j < 4; j++) o[i][j] = 0.f;
    __syncthreads();

    for (int kt = 0; kt <= qt; kt++) {
        {
            int r  = tid >> 2;
            int d0 = (tid & 3) * 16;
            const float* kp = base + (size_t)(kt * 64 + r) * C3_ + C_ + h * 64 + d0;
            const float* vp = kp + C_;
#pragma unroll
            for (int i = 0; i < 4; i++) {
                float4 v = *reinterpret_cast<const float4*>(&kp[4 * i]);
                Ks[(d0 + 4 * i + 0) * 64 + r] = v.x;
                Ks[(d0 + 4 * i + 1) * 64 + r] = v.y;
                Ks[(d0 + 4 * i + 2) * 64 + r] = v.z;
                Ks[(d0 + 4 * i + 3) * 64 + r] = v.w;
            }
#pragma unroll
            for (int i = 0; i < 4; i++) {
                float4 v = *reinterpret_cast<const float4*>(&vp[4 * i]);
                *reinterpret_cast<float4*>(&Vs[r * 64 + d0 + 4 * i]) = v;
            }
        }
        __syncthreads();

        float cS[4][4];
#pragma unroll
        for (int i = 0; i < 4; i++)
#pragma unroll
            for (int j = 0; j < 4; j++) cS[i][j] = 0.f;
        for (int d = 0; d < 64; d++) {
            float4 aq = *reinterpret_cast<const float4*>(&Qs[d * 64 + 4 * ty]);
            float4 bk = *reinterpret_cast<const float4*>(&Ks[d * 64 + 4 * tx]);
            float a[4] = {aq.x, aq.y, aq.z, aq.w};
            float bb[4] = {bk.x, bk.y, bk.z, bk.w};
#pragma unroll
            for (int i = 0; i < 4; i++)
#pragma unroll
                for (int j = 0; j < 4; j++) cS[i][j] += a[i] * bb[j];
        }

        float al[4];
        bool diag = (kt == qt);
#pragma unroll
        for (int i = 0; i < 4; i++) {
            int r  = 4 * ty + i;
            int qg = qt * 64 + r;
            float rmax = -1e30f;
#pragma unroll
            for (int j = 0; j < 4; j++) {
                float s = cS[i][j] * scale;
                if (diag && (kt * 64 + 4 * tx + j) > qg) s = -1e30f;
                cS[i][j] = s;
                rmax = fmaxf(rmax, s);
            }
#pragma unroll
            for (int off = 8; off > 0; off >>= 1)
                rmax = fmaxf(rmax, __shfl_xor_sync(0xffffffffu, rmax, off));
            float mo = mrow[r];
            float mn = fmaxf(mo, rmax);
            float sum = 0.f;
#pragma unroll
            for (int j = 0; j < 4; j++) {
                float p = __expf(cS[i][j] - mn);
                cS[i][j] = p;
                sum += p;
            }
#pragma unroll
            for (int off = 8; off > 0; off >>= 1)
                sum += __shfl_xor_sync(0xffffffffu, sum, off);
            al[i] = __expf(mo - mn);
            if (tx == 0) {
                mrow[r] = mn;
                lrow[r] = lrow[r] * al[i] + sum;
            }
        }
#pragma unroll
        for (int i = 0; i < 4; i++) {
#pragma unroll
            for (int j = 0; j < 4; j++) {
                o[i][j] *= al[i];
                Ps[(4 * ty + i) * 65 + 4 * tx + j] = cS[i][j];
            }
        }
        __syncthreads();

        for (int k = 0; k < 64; k++) {
            float a0 = Ps[(4 * ty + 0) * 65 + k];
            float a1 = Ps[(4 * ty + 1) * 65 + k];
            float a2 = Ps[(4 * ty + 2) * 65 + k];
            float a3 = Ps[(4 * ty + 3) * 65 + k];
            float4 bv = *reinterpret_cast<const float4*>(&Vs[k * 64 + 4 * tx]);
            float bb[4] = {bv.x, bv.y, bv.z, bv.w};
#pragma unroll
            for (int j = 0; j < 4; j++) {
                o[0][j] += a0 * bb[j];
                o[1][j] += a1 * bb[j];
                o[2][j] += a2 * bb[j];
                o[3][j] += a3 * bb[j];
            }
        }
        __syncthreads();
    }

#pragma unroll
    for (int i = 0; i < 4; i++) {
        int r = 4 * ty + i;
        float linv = 1.f / lrow[r];
        size_t row = (size_t)(b * T_ + qt * 64 + r) * C_ + h * 64 + 4 * tx;
        float4 v;
        v.x = tf32_round(o[i][0] * linv); v.y = tf32_round(o[i][1] * linv);
        v.z = tf32_round(o[i][2] * linv); v.w = tf32_round(o[i][3] * linv);
        *reinterpret_cast<float4*>(&y[row]) = v;
    }
}

// ---------------- host launcher ----------------
extern "C" void kernel_launch(void* const* d_in, const int* in_sizes, int n_in,
                              void* d_out, int out_size) {
    const int*   idxw    = (const int*)  d_in[0];
    const float* tok_emb = (const float*)d_in[1];
    const float* pos_emb = (const float*)d_in[2];
    const float* ln1_s   = (const float*)d_in[3];
    const float* ln1_b   = (const float*)d_in[4];
    const float* Wqkv    = (const float*)d_in[5];
    const float* bqkv    = (const float*)d_in[6];
    const float* Wo      = (const float*)d_in[7];
    const float* bo      = (const float*)d_in[8];
    const float* ln2_s   = (const float*)d_in[9];
    const float* ln2_b   = (const float*)d_in[10];
    const float* Wfc     = (const float*)d_in[11];
    const float* bfc     = (const float*)d_in[12];
    const float* Wpr     = (const float*)d_in[13];
    const float* bpr     = (const float*)d_in[14];
    const float* lnf_s   = (const float*)d_in[15];
    const float* lnf_b   = (const float*)d_in[16];
    const float* Whead   = (const float*)d_in[17];
    float* out = (float*)d_out;

    float *x, *h, *qkv, *y, *ff, *part, *Wp, *Wqkv_t, *Wo_t, *Wfc_t, *Wpr_t;
    cudaGetSymbolAddress((void**)&x,      g_x);
    cudaGetSymbolAddress((void**)&h,      g_h);
    cudaGetSymbolAddress((void**)&qkv,    g_qkv);
    cudaGetSymbolAddress((void**)&y,      g_y);
    cudaGetSymbolAddress((void**)&ff,     g_ff);
    cudaGetSymbolAddress((void**)&part,   g_part);
    cudaGetSymbolAddress((void**)&Wp,     g_Wp);
    cudaGetSymbolAddress((void**)&Wqkv_t, g_Wqkv_t);
    cudaGetSymbolAddress((void**)&Wo_t,   g_Wo_t);
    cudaGetSymbolAddress((void**)&Wfc_t,  g_Wfc_t);
    cudaGetSymbolAddress((void**)&Wpr_t,  g_Wpr_t);

    cudaFuncSetAttribute(attn_flash_kernel,
                         cudaFuncAttributeMaxDynamicSharedMemorySize, ATT_SMEM);
    cudaFuncSetAttribute(tgemm_kernel,
                         cudaFuncAttributeMaxDynamicSharedMemorySize, GEMM_SMEM);

    detect_idx_kernel<<<1, 256>>>(idxw);
    embed_kernel<<<(BT_ * C_ + 255) / 256, 256>>>(idxw, tok_emb, pos_emb, x);
    padW_kernel<<<(C_ * VP_ + 255) / 256, 256>>>(Whead, Wp);
    round_all_kernel<<<(N4_ALL + 255) / 256, 256>>>(Wqkv, Wo, Wfc, Wpr,
                                                    Wqkv_t, Wo_t, Wfc_t, Wpr_t);

    dim3 gQKV(C3_ / GBN, BT_ / GBM);
    dim3 gPROJ_SK(C_ / GBN, BT_ / GBM, SK_);   // 6 x 16 x 3 = 288 CTAs
    dim3 gFC(FF_ / GBN, BT_ / GBM);
    dim3 gHEAD(VP_ / GBN, BT_ / GBM);
    dim3 gATT(T_ / 64, H_, B_);
    int  rblocks = (BT_ * C_ / 4 + 255) / 256;

    for (int l = 0; l < L_; l++) {
        ln_kernel<<<BT_ / 8, 256>>>(x, h, ln1_s + (size_t)l * C_, ln1_b + (size_t)l * C_);
        tgemm_kernel<<<gQKV, 256, GEMM_SMEM>>>(h, Wqkv_t + (size_t)l * C_ * C3_,
                                    bqkv + (size_t)l * C3_, nullptr, qkv,
                                    BT_, C3_, C_, C_, C3_, 0, 0);
        attn_flash_kernel<<<gATT, 256, ATT_SMEM>>>(qkv, y);
        // Wo: split-K=3, klen = 768/3 = 256, partials then reduce into x
        tgemm_kernel<<<gPROJ_SK, 256, GEMM_SMEM>>>(y, Wo_t + (size_t)l * C_ * C_,
                                     nullptr, nullptr, part,
                                     BT_, C_, C_ / SK_, C_, C_, 0, 0);
        reduce_split_kernel<<<rblocks, 256>>>(part, bo + (size_t)l * C_, x);
        ln_kernel<<<BT_ / 8, 256>>>(x, h, ln2_s + (size_t)l * C_, ln2_b + (size_t)l * C_);
        tgemm_kernel<<<gFC, 256, GEMM_SMEM>>>(h, Wfc_t + (size_t)l * C_ * FF_,
                                   bfc + (size_t)l * FF_, nullptr, ff,
                                   BT_, FF_, C_, C_, FF_, 1, 1);
        // Wpr: split-K=3, klen = 3072/3 = 1024
        tgemm_kernel<<<gPROJ_SK, 256, GEMM_SMEM>>>(ff, Wpr_t + (size_t)l * FF_ * C_,
                                     nullptr, nullptr, part,
                                     BT_, C_, FF_ / SK_, FF_, C_, 0, 0);
        reduce_split_kernel<<<rblocks, 256>>>(part, bpr + (size_t)l * C_, x);
    }

    ln_kernel<<<BT_ / 8, 256>>>(x, h, lnf_s, lnf_b);
    tgemm_kernel<<<gHEAD, 256, GEMM_SMEM>>>(h, Wp, nullptr, nullptr, out,
                                 BT_, V_, C_, C_, VP_, 0, 0);
}

// round 15
// speedup vs baseline: 1.1213x; 1.0061x over previous
#include <cuda_runtime.h>
#include <math.h>
#include <stdint.h>

// ---------------- problem constants ----------------
#define B_   2
#define T_   1024
#define C_   768
#define H_   12
#define D_   64
#define L_   12
#define FF_  3072
#define V_   50257
#define VP_  50304          // 393 * 128
#define BT_  (B_ * T_)      // 2048
#define C3_  (3 * C_)       // 2304
#define SK_  3              // split-K factor for N=768 GEMMs

// ---------------- device scratch ----------------
__device__ float g_x  [BT_ * C_];
__device__ float g_h  [BT_ * C_];
__device__ float g_qkv[BT_ * C3_];
__device__ float g_y  [BT_ * C_];
__device__ float g_ff [BT_ * FF_];
__device__ float g_part[SK_ * BT_ * C_];     // split-K partials
__device__ float g_Wp [C_ * VP_];            // padded + tf32-rounded Whead
__device__ float g_Wqkv_t[L_ * C_ * C3_];    // tf32-rounded weights
__device__ float g_Wo_t  [L_ * C_ * C_];
__device__ float g_Wfc_t [L_ * C_ * FF_];
__device__ float g_Wpr_t [L_ * FF_ * C_];
__device__ int   g_idx_is64;

// sizes (in float4 units) for the merged rounding kernel
#define N4_QKV (L_ * C_ * C3_ / 4)
#define N4_WO  (L_ * C_ * C_ / 4)
#define N4_FC  (L_ * C_ * FF_ / 4)
#define N4_PR  (L_ * FF_ * C_ / 4)
#define N4_ALL (N4_QKV + N4_WO + N4_FC + N4_PR)

// ---------------- tf32 helper ----------------
__device__ __forceinline__ uint32_t tf32_of(float x) {
    uint32_t u;
    asm("cvt.rna.tf32.f32 %0, %1;" : "=r"(u) : "f"(x));
    return u;
}
__device__ __forceinline__ float tf32_round(float x) {
    return __uint_as_float(tf32_of(x));
}

// ---------------- idx dtype detection ----------------
__global__ void detect_idx_kernel(const int* w) {
    __shared__ int found;
    if (threadIdx.x == 0) found = 0;
    __syncthreads();
    for (int i = threadIdx.x; i < BT_ / 2; i += blockDim.x)
        if (w[2 * i + 1] != 0) found = 1;
    __syncthreads();
    if (threadIdx.x == 0) g_idx_is64 = found ? 0 : 1;
}

// ---------------- embedding ----------------
__global__ void embed_kernel(const int* idxw, const float* tok, const float* pos,
                             float* x) {
    int i = blockIdx.x * blockDim.x + threadIdx.x;
    if (i >= BT_ * C_) return;
    int bt = i / C_;
    int c  = i - bt * C_;
    int t  = bt % T_;
    int token = g_idx_is64 ? idxw[2 * bt] : idxw[bt];
    x[i] = tok[(size_t)token * C_ + c] + pos[t * C_ + c];
}

// ---------------- merged tf32 pre-round for all four weight groups ----------------
__global__ void round_all_kernel(const float* __restrict__ Wqkv,
                                 const float* __restrict__ Wo,
                                 const float* __restrict__ Wfc,
                                 const float* __restrict__ Wpr,
                                 float* __restrict__ Dqkv,
                                 float* __restrict__ Do_,
                                 float* __restrict__ Dfc,
                                 float* __restrict__ Dpr) {
    int i = blockIdx.x * blockDim.x + threadIdx.x;
    if (i >= N4_ALL) return;
    const float4* src;
    float4* dst;
    int j = i;
    if (j < N4_QKV) {
        src = reinterpret_cast<const float4*>(Wqkv);
        dst = reinterpret_cast<float4*>(Dqkv);
    } else if ((j -= N4_QKV) < N4_WO) {
        src = reinterpret_cast<const float4*>(Wo);
        dst = reinterpret_cast<float4*>(Do_);
    } else if ((j -= N4_WO) < N4_FC) {
        src = reinterpret_cast<const float4*>(Wfc);
        dst = reinterpret_cast<float4*>(Dfc);
    } else {
        j -= N4_FC;
        src = reinterpret_cast<const float4*>(Wpr);
        dst = reinterpret_cast<float4*>(Dpr);
    }
    float4 v = src[j];
    v.x = tf32_round(v.x); v.y = tf32_round(v.y);
    v.z = tf32_round(v.z); v.w = tf32_round(v.w);
    dst[j] = v;
}

// ---------------- pad + round Whead to stride VP_ ----------------
__global__ void padW_kernel(const float* __restrict__ W, float* __restrict__ Wp) {
    int i = blockIdx.x * blockDim.x + threadIdx.x;
    if (i >= C_ * VP_) return;
    int row = i / VP_;
    int col = i - row * VP_;
    Wp[i] = (col < V_) ? tf32_round(W[(size_t)row * V_ + col]) : 0.f;
}

// ---------------- layernorm: one warp per row, 8 rows per CTA ----------------
__global__ __launch_bounds__(256)
void ln_kernel(const float* __restrict__ x, float* __restrict__ out,
               const float* __restrict__ s, const float* __restrict__ b) {
    int warp = threadIdx.x >> 5;
    int lane = threadIdx.x & 31;
    int row  = blockIdx.x * 8 + warp;
    const float* xr = x + (size_t)row * C_;
    float4 v[6];
    float sum = 0.f, sq = 0.f;
#pragma unroll
    for (int i = 0; i < 6; i++) {
        v[i] = *reinterpret_cast<const float4*>(&xr[(i * 32 + lane) * 4]);
        sum += v[i].x + v[i].y + v[i].z + v[i].w;
        sq  += v[i].x * v[i].x + v[i].y * v[i].y
             + v[i].z * v[i].z + v[i].w * v[i].w;
    }
#pragma unroll
    for (int off = 16; off > 0; off >>= 1) {
        sum += __shfl_xor_sync(0xffffffffu, sum, off);
        sq  += __shfl_xor_sync(0xffffffffu, sq,  off);
    }
    float mu  = sum * (1.f / C_);
    float var = sq * (1.f / C_) - mu * mu;
    float inv = rsqrtf(var + 1e-5f);
    float* orow = out + (size_t)row * C_;
#pragma unroll
    for (int i = 0; i < 6; i++) {
        int c = (i * 32 + lane) * 4;
        float4 sv = *reinterpret_cast<const float4*>(&s[c]);
        float4 bv = *reinterpret_cast<const float4*>(&b[c]);
        float4 o;
        o.x = tf32_round((v[i].x - mu) * inv * sv.x + bv.x);
        o.y = tf32_round((v[i].y - mu) * inv * sv.y + bv.y);
        o.z = tf32_round((v[i].z - mu) * inv * sv.z + bv.z);
        o.w = tf32_round((v[i].w - mu) * inv * sv.w + bv.w);
        *reinterpret_cast<float4*>(&orow[c]) = o;
    }
}

// ---------------- fused split-K reduce + residual + bias + layernorm ----------------
// Per row: xnew = x + p0 + p1 + p2 + bias; x <- xnew; out <- tf32(LN(xnew)).
__global__ __launch_bounds__(256)
void ln_red_kernel(const float* __restrict__ part, const float* __restrict__ bias,
                   float* __restrict__ x, float* __restrict__ out,
                   const float* __restrict__ s, const float* __restrict__ b) {
    int warp = threadIdx.x >> 5;
    int lane = threadIdx.x & 31;
    int row  = blockIdx.x * 8 + warp;
    const size_t roff = (size_t)row * C_;
    const size_t MN   = (size_t)BT_ * C_;
    float* xr = x + roff;
    const float* p0 = part + roff;
    const float* p1 = part + MN + roff;
    const float* p2 = part + 2 * MN + roff;

    float4 v[6];
    float sum = 0.f, sq = 0.f;
#pragma unroll
    for (int i = 0; i < 6; i++) {
        int c = (i * 32 + lane) * 4;
        float4 xv = *reinterpret_cast<const float4*>(&xr[c]);
        float4 a0 = *reinterpret_cast<const float4*>(&p0[c]);
        float4 a1 = *reinterpret_cast<const float4*>(&p1[c]);
        float4 a2 = *reinterpret_cast<const float4*>(&p2[c]);
        float4 bv = *reinterpret_cast<const float4*>(&bias[c]);
        float4 nv;
        nv.x = xv.x + a0.x + a1.x + a2.x + bv.x;
        nv.y = xv.y + a0.y + a1.y + a2.y + bv.y;
        nv.z = xv.z + a0.z + a1.z + a2.z + bv.z;
        nv.w = xv.w + a0.w + a1.w + a2.w + bv.w;
        *reinterpret_cast<float4*>(&xr[c]) = nv;
        v[i] = nv;
        sum += nv.x + nv.y + nv.z + nv.w;
        sq  += nv.x * nv.x + nv.y * nv.y + nv.z * nv.z + nv.w * nv.w;
    }
#pragma unroll
    for (int off = 16; off > 0; off >>= 1) {
        sum += __shfl_xor_sync(0xffffffffu, sum, off);
        sq  += __shfl_xor_sync(0xffffffffu, sq,  off);
    }
    float mu  = sum * (1.f / C_);
    float var = sq * (1.f / C_) - mu * mu;
    float inv = rsqrtf(var + 1e-5f);
    float* orow = out + roff;
#pragma unroll
    for (int i = 0; i < 6; i++) {
        int c = (i * 32 + lane) * 4;
        float4 sv = *reinterpret_cast<const float4*>(&s[c]);
        float4 bv = *reinterpret_cast<const float4*>(&b[c]);
        float4 o;
        o.x = tf32_round((v[i].x - mu) * inv * sv.x + bv.x);
        o.y = tf32_round((v[i].y - mu) * inv * sv.y + bv.y);
        o.z = tf32_round((v[i].z - mu) * inv * sv.z + bv.z);
        o.w = tf32_round((v[i].w - mu) * inv * sv.w + bv.w);
        *reinterpret_cast<float4*>(&orow[c]) = o;
    }
}

// ---------------- cp.async helpers ----------------
__device__ __forceinline__ uint32_t smem_u32(const void* p) {
    return (uint32_t)__cvta_generic_to_shared(p);
}
__device__ __forceinline__ void cp16(uint32_t dst, const void* src) {
    asm volatile("cp.async.ca.shared.global [%0], [%1], 16;" :: "r"(dst), "l"(src));
}
__device__ __forceinline__ void cp_commit() {
    asm volatile("cp.async.commit_group;");
}
template <int Ngrp>
__device__ __forceinline__ void cp_wait() {
    asm volatile("cp.async.wait_group %0;" :: "n"(Ngrp));
}

__device__ __forceinline__ void mma_tf32(float* c, const uint32_t* a, const uint32_t* b) {
    asm volatile(
        "mma.sync.aligned.m16n8k8.row.col.f32.tf32.tf32.f32 "
        "{%0,%1,%2,%3}, {%4,%5,%6,%7}, {%8,%9}, {%0,%1,%2,%3};"
        : "+f"(c[0]), "+f"(c[1]), "+f"(c[2]), "+f"(c[3])
        : "r"(a[0]), "r"(a[1]), "r"(a[2]), "r"(a[3]), "r"(b[0]), "r"(b[1]));
}

// ---------------- tf32 GEMM: 128x128, BK=16, 3-stage cp.async (R12 verified) ------
// K = per-CTA K length; ldA = A row stride. blockIdx.z = split-K slice.
// gridDim.z > 1 => write raw partial accumulators to Cout + z*M*Nout.
#define GBM 128
#define GBN 128
#define GBK 16
#define ALD 20
#define BLD 136
#define A_ST (GBM * ALD)
#define B_ST (GBK * BLD)
#define GEMM_SMEM (3 * (A_ST + B_ST) * 4)

__global__ __launch_bounds__(256)
void tgemm_kernel(const float* __restrict__ A, const float* __restrict__ W,
                  const float* __restrict__ bias, const float* __restrict__ Res,
                  float* __restrict__ Cout, int M, int Nout, int K, int ldA,
                  int ldw, int act, int rnd) {
    extern __shared__ float smg[];
    float* sA = smg;
    float* sB = smg + 3 * A_ST;

    int z = blockIdx.z;
    const float* Ab = A + (size_t)z * K;
    const float* Wb = W + (size_t)z * K * ldw;

    int bn = blockIdx.x * GBN;
    int bm = blockIdx.y * GBM;
    int tid  = threadIdx.x;
    int lane = tid & 31;
    int warp = tid >> 5;
    int wm = warp >> 2;
    int wn = warp & 3;
    int g   = lane >> 2;
    int tig = lane & 3;

    int a_r  = tid >> 2;
    int a_f4 = (tid & 3) * 4;
    int b_r  = tid >> 5;
    int b_c4 = (tid & 31) * 4;

    auto load_tiles = [&](int s, int k0) {
        float* As = sA + s * A_ST;
        float* Bs = sB + s * B_ST;
#pragma unroll
        for (int it = 0; it < 2; it++) {
            int row = a_r + it * 64;
            cp16(smem_u32(&As[row * ALD + a_f4]),
                 &Ab[(size_t)(bm + row) * ldA + k0 + a_f4]);
        }
#pragma unroll
        for (int it = 0; it < 2; it++) {
            int kr = b_r + it * 8;
            cp16(smem_u32(&Bs[kr * BLD + b_c4]),
                 &Wb[(size_t)(k0 + kr) * ldw + bn + b_c4]);
        }
    };

    float acc[4][4][4];
#pragma unroll
    for (int mi = 0; mi < 4; mi++)
#pragma unroll
        for (int ni = 0; ni < 4; ni++)
#pragma unroll
            for (int e = 0; e < 4; e++) acc[mi][ni][e] = 0.f;

    int KT = K / GBK;
    load_tiles(0, 0);
    cp_commit();
    if (KT > 1) { load_tiles(1, GBK); cp_commit(); }

    for (int kt = 0; kt < KT; kt++) {
        if (kt + 1 < KT) cp_wait<1>(); else cp_wait<0>();
        __syncthreads();
        if (kt + 2 < KT) { load_tiles((kt + 2) % 3, (kt + 2) * GBK); cp_commit(); }

        const uint32_t* As = reinterpret_cast<const uint32_t*>(sA + (kt % 3) * A_ST);
        const uint32_t* Bs = reinterpret_cast<const uint32_t*>(sB + (kt % 3) * B_ST);
#pragma unroll
        for (int ks = 0; ks < 2; ks++) {
            int kb = ks * 8;
            uint32_t af[4][4], bf[4][2];
#pragma unroll
            for (int mi = 0; mi < 4; mi++) {
                int m0 = wm * 64 + mi * 16;
                af[mi][0] = As[(m0 + g    ) * ALD + kb + tig    ];
                af[mi][1] = As[(m0 + g + 8) * ALD + kb + tig    ];
                af[mi][2] = As[(m0 + g    ) * ALD + kb + tig + 4];
                af[mi][3] = As[(m0 + g + 8) * ALD + kb + tig + 4];
            }
#pragma unroll
            for (int ni = 0; ni < 4; ni++) {
                int n0 = wn * 32 + ni * 8;
                bf[ni][0] = Bs[(kb + tig    ) * BLD + n0 + g];
                bf[ni][1] = Bs[(kb + tig + 4) * BLD + n0 + g];
            }
#pragma unroll
            for (int mi = 0; mi < 4; mi++)
#pragma unroll
                for (int ni = 0; ni < 4; ni++)
                    mma_tf32(acc[mi][ni], af[mi], bf[ni]);
        }
    }
    __syncthreads();

    if (gridDim.z > 1) {
        float* P = Cout + (size_t)z * M * Nout;
#pragma unroll
        for (int mi = 0; mi < 4; mi++) {
            int r0 = bm + wm * 64 + mi * 16 + g;
#pragma unroll
            for (int ni = 0; ni < 4; ni++) {
                int col0 = bn + wn * 32 + ni * 8 + 2 * tig;
#pragma unroll
                for (int ep = 0; ep < 4; ep += 2) {
                    int row = r0 + (ep >> 1) * 8;
                    float2 st = {acc[mi][ni][ep], acc[mi][ni][ep + 1]};
                    *reinterpret_cast<float2*>(&P[(size_t)row * Nout + col0]) = st;
                }
            }
        }
        return;
    }

    bool evenN = ((Nout & 1) == 0);
#pragma unroll
    for (int mi = 0; mi < 4; mi++) {
        int r0 = bm + wm * 64 + mi * 16 + g;
#pragma unroll
        for (int ni = 0; ni < 4; ni++) {
            int col0 = bn + wn * 32 + ni * 8 + 2 * tig;
#pragma unroll
            for (int ep = 0; ep < 4; ep += 2) {
                int row = r0 + (ep >> 1) * 8;
                float v0 = acc[mi][ni][ep];
                float v1 = acc[mi][ni][ep + 1];
                if (bias) { v0 += bias[col0]; v1 += bias[col0 + 1]; }
                if (act == 1) {
                    v0 = 0.5f * v0 * (1.f + erff(v0 * 0.70710678118654752f));
                    v1 = 0.5f * v1 * (1.f + erff(v1 * 0.70710678118654752f));
                }
                if (rnd) { v0 = tf32_round(v0); v1 = tf32_round(v1); }
                size_t o = (size_t)row * Nout + col0;
                if (evenN) {
                    if (Res) { v0 += Res[o]; v1 += Res[o + 1]; }
                    float2 st = {v0, v1};
                    *reinterpret_cast<float2*>(&Cout[o]) = st;
                } else {
                    if (col0 < Nout) {
                        if (Res) v0 += Res[o];
                        Cout[o] = v0;
                    }
                    if (col0 + 1 < Nout) {
                        if (Res) v1 += Res[o + 1];
                        Cout[o + 1] = v1;
                    }
                }
            }
        }
    }
}

// ---------------- flash attention: one CTA per (b, h, 64-q tile) ----------------
#define ATT_SMEM ((3 * 64 * 64 + 64 * 65 + 128) * 4)

__global__ __launch_bounds__(256)
void attn_flash_kernel(const float* __restrict__ qkv, float* __restrict__ y) {
    extern __shared__ float sm[];
    float* Qs   = sm;
    float* Ks   = Qs + 64 * 64;
    float* Vs   = Ks + 64 * 64;
    float* Ps   = Vs + 64 * 64;
    float* mrow = Ps + 64 * 65;
    float* lrow = mrow + 64;

    int qt  = blockIdx.x;
    int h   = blockIdx.y;
    int b   = blockIdx.z;
    int tid = threadIdx.x;
    int tx  = tid & 15;
    int ty  = tid >> 4;
    const float scale = 0.125f;
    const float* base = qkv + (size_t)b * T_ * C3_;

    {
        int r  = tid >> 2;
        int d0 = (tid & 3) * 16;
        const float* qp = base + (size_t)(qt * 64 + r) * C3_ + h * 64 + d0;
#pragma unroll
        for (int i = 0; i < 4; i++) {
            float4 v = *reinterpret_cast<const float4*>(&qp[4 * i]);
            Qs[(d0 + 4 * i + 0) * 64 + r] = v.x;
            Qs[(d0 + 4 * i + 1) * 64 + r] = v.y;
            Qs[(d0 + 4 * i + 2) * 64 + r] = v.z;
            Qs[(d0 + 4 * i + 3) * 64 + r] = v.w;
        }
    }
    if (tid < 64) { mrow[tid] = -1e30f; lrow[tid] = 0.f; }

    float o[4][4];
#pragma unroll
    for (int i = 0; i < 4; i++)
#pragma unroll
        for (int j = 0; j < 4; j++) o[i][j] = 0.f;
    __syncthreads();

    for (int kt = 0; kt <= qt; kt++) {
        {
            int r  = tid >> 2;
            int d0 = (tid & 3) * 16;
            const float* kp = base + (size_t)(kt * 64 + r) * C3_ + C_ + h * 64 + d0;
            const float* vp = kp + C_;
#pragma unroll
            for (int i = 0; i < 4; i++) {
                float4 v = *reinterpret_cast<const float4*>(&kp[4 * i]);
                Ks[(d0 + 4 * i + 0) * 64 + r] = v.x;
                Ks[(d0 + 4 * i + 1) * 64 + r] = v.y;
                Ks[(d0 + 4 * i + 2) * 64 + r] = v.z;
                Ks[(d0 + 4 * i + 3) * 64 + r] = v.w;
            }
#pragma unroll
            for (int i = 0; i < 4; i++) {
                float4 v = *reinterpret_cast<const float4*>(&vp[4 * i]);
                *reinterpret_cast<float4*>(&Vs[r * 64 + d0 + 4 * i]) = v;
            }
        }
        __syncthreads();

        float cS[4][4];
#pragma unroll
        for (int i = 0; i < 4; i++)
#pragma unroll
            for (int j = 0; j < 4; j++) cS[i][j] = 0.f;
        for (int d = 0; d < 64; d++) {
            float4 aq = *reinterpret_cast<const float4*>(&Qs[d * 64 + 4 * ty]);
            float4 bk = *reinterpret_cast<const float4*>(&Ks[d * 64 + 4 * tx]);
            float a[4] = {aq.x, aq.y, aq.z, aq.w};
            float bb[4] = {bk.x, bk.y, bk.z, bk.w};
#pragma unroll
            for (int i = 0; i < 4; i++)
#pragma unroll
                for (int j = 0; j < 4; j++) cS[i][j] += a[i] * bb[j];
        }

        float al[4];
        bool diag = (kt == qt);
#pragma unroll
        for (int i = 0; i < 4; i++) {
            int r  = 4 * ty + i;
            int qg = qt * 64 + r;
            float rmax = -1e30f;
#pragma unroll
            for (int j = 0; j < 4; j++) {
                float s = cS[i][j] * scale;
                if (diag && (kt * 64 + 4 * tx + j) > qg) s = -1e30f;
                cS[i][j] = s;
                rmax = fmaxf(rmax, s);
            }
#pragma unroll
            for (int off = 8; off > 0; off >>= 1)
                rmax = fmaxf(rmax, __shfl_xor_sync(0xffffffffu, rmax, off));
            float mo = mrow[r];
            float mn = fmaxf(mo, rmax);
            float sum = 0.f;
#pragma unroll
            for (int j = 0; j < 4; j++) {
                float p = __expf(cS[i][j] - mn);
                cS[i][j] = p;
                sum += p;
            }
#pragma unroll
            for (int off = 8; off > 0; off >>= 1)
                sum += __shfl_xor_sync(0xffffffffu, sum, off);
            al[i] = __expf(mo - mn);
            if (tx == 0) {
                mrow[r] = mn;
                lrow[r] = lrow[r] * al[i] + sum;
            }
        }
#pragma unroll
        for (int i = 0; i < 4; i++) {
#pragma unroll
            for (int j = 0; j < 4; j++) {
                o[i][j] *= al[i];
                Ps[(4 * ty + i) * 65 + 4 * tx + j] = cS[i][j];
            }
        }
        __syncthreads();

        for (int k = 0; k < 64; k++) {
            float a0 = Ps[(4 * ty + 0) * 65 + k];
            float a1 = Ps[(4 * ty + 1) * 65 + k];
            float a2 = Ps[(4 * ty + 2) * 65 + k];
            float a3 = Ps[(4 * ty + 3) * 65 + k];
            float4 bv = *reinterpret_cast<const float4*>(&Vs[k * 64 + 4 * tx]);
            float bb[4] = {bv.x, bv.y, bv.z, bv.w};
#pragma unroll
            for (int j = 0; j < 4; j++) {
                o[0][j] += a0 * bb[j];
                o[1][j] += a1 * bb[j];
                o[2][j] += a2 * bb[j];
                o[3][j] += a3 * bb[j];
            }
        }
        __syncthreads();
    }

#pragma unroll
    for (int i = 0; i < 4; i++) {
        int r = 4 * ty + i;
        float linv = 1.f / lrow[r];
        size_t row = (size_t)(b * T_ + qt * 64 + r) * C_ + h * 64 + 4 * tx;
        float4 v;
        v.x = tf32_round(o[i][0] * linv); v.y = tf32_round(o[i][1] * linv);
        v.z = tf32_round(o[i][2] * linv); v.w = tf32_round(o[i][3] * linv);
        *reinterpret_cast<float4*>(&y[row]) = v;
    }
}

// ---------------- host launcher ----------------
extern "C" void kernel_launch(void* const* d_in, const int* in_sizes, int n_in,
                              void* d_out, int out_size) {
    const int*   idxw    = (const int*)  d_in[0];
    const float* tok_emb = (const float*)d_in[1];
    const float* pos_emb = (const float*)d_in[2];
    const float* ln1_s   = (const float*)d_in[3];
    const float* ln1_b   = (const float*)d_in[4];
    const float* Wqkv    = (const float*)d_in[5];
    const float* bqkv    = (const float*)d_in[6];
    const float* Wo      = (const float*)d_in[7];
    const float* bo      = (const float*)d_in[8];
    const float* ln2_s   = (const float*)d_in[9];
    const float* ln2_b   = (const float*)d_in[10];
    const float* Wfc     = (const float*)d_in[11];
    const float* bfc     = (const float*)d_in[12];
    const float* Wpr     = (const float*)d_in[13];
    const float* bpr     = (const float*)d_in[14];
    const float* lnf_s   = (const float*)d_in[15];
    const float* lnf_b   = (const float*)d_in[16];
    const float* Whead   = (const float*)d_in[17];
    float* out = (float*)d_out;

    float *x, *h, *qkv, *y, *ff, *part, *Wp, *Wqkv_t, *Wo_t, *Wfc_t, *Wpr_t;
    cudaGetSymbolAddress((void**)&x,      g_x);
    cudaGetSymbolAddress((void**)&h,      g_h);
    cudaGetSymbolAddress((void**)&qkv,    g_qkv);
    cudaGetSymbolAddress((void**)&y,      g_y);
    cudaGetSymbolAddress((void**)&ff,     g_ff);
    cudaGetSymbolAddress((void**)&part,   g_part);
    cudaGetSymbolAddress((void**)&Wp,     g_Wp);
    cudaGetSymbolAddress((void**)&Wqkv_t, g_Wqkv_t);
    cudaGetSymbolAddress((void**)&Wo_t,   g_Wo_t);
    cudaGetSymbolAddress((void**)&Wfc_t,  g_Wfc_t);
    cudaGetSymbolAddress((void**)&Wpr_t,  g_Wpr_t);

    cudaFuncSetAttribute(attn_flash_kernel,
                         cudaFuncAttributeMaxDynamicSharedMemorySize, ATT_SMEM);
    cudaFuncSetAttribute(tgemm_kernel,
                         cudaFuncAttributeMaxDynamicSharedMemorySize, GEMM_SMEM);

    detect_idx_kernel<<<1, 256>>>(idxw);
    embed_kernel<<<(BT_ * C_ + 255) / 256, 256>>>(idxw, tok_emb, pos_emb, x);
    padW_kernel<<<(C_ * VP_ + 255) / 256, 256>>>(Whead, Wp);
    round_all_kernel<<<(N4_ALL + 255) / 256, 256>>>(Wqkv, Wo, Wfc, Wpr,
                                                    Wqkv_t, Wo_t, Wfc_t, Wpr_t);

    dim3 gQKV(C3_ / GBN, BT_ / GBM);
    dim3 gPROJ_SK(C_ / GBN, BT_ / GBM, SK_);   // 6 x 16 x 3 = 288 CTAs
    dim3 gFC(FF_ / GBN, BT_ / GBM);
    dim3 gHEAD(VP_ / GBN, BT_ / GBM);
    dim3 gATT(T_ / 64, H_, B_);

    // layer 0 ln1 (no preceding split-K reduce)
    ln_kernel<<<BT_ / 8, 256>>>(x, h, ln1_s, ln1_b);

    for (int l = 0; l < L_; l++) {
        tgemm_kernel<<<gQKV, 256, GEMM_SMEM>>>(h, Wqkv_t + (size_t)l * C_ * C3_,
                                    bqkv + (size_t)l * C3_, nullptr, qkv,
                                    BT_, C3_, C_, C_, C3_, 0, 0);
        attn_flash_kernel<<<gATT, 256, ATT_SMEM>>>(qkv, y);
        // Wo: split-K=3 partials, then fused reduce + ln2
        tgemm_kernel<<<gPROJ_SK, 256, GEMM_SMEM>>>(y, Wo_t + (size_t)l * C_ * C_,
                                     nullptr, nullptr, part,
                                     BT_, C_, C_ / SK_, C_, C_, 0, 0);
        ln_red_kernel<<<BT_ / 8, 256>>>(part, bo + (size_t)l * C_, x, h,
                                        ln2_s + (size_t)l * C_, ln2_b + (size_t)l * C_);
        tgemm_kernel<<<gFC, 256, GEMM_SMEM>>>(h, Wfc_t + (size_t)l * C_ * FF_,
                                   bfc + (size_t)l * FF_, nullptr, ff,
                                   BT_, FF_, C_, C_, FF_, 1, 1);
        // Wpr: split-K=3 partials, then fused reduce + next ln1 (or lnf)
        tgemm_kernel<<<gPROJ_SK, 256, GEMM_SMEM>>>(ff, Wpr_t + (size_t)l * FF_ * C_,
                                     nullptr, nullptr, part,
                                     BT_, C_, FF_ / SK_, FF_, C_, 0, 0);
        if (l + 1 < L_) {
            ln_red_kernel<<<BT_ / 8, 256>>>(part, bpr + (size_t)l * C_, x, h,
                                            ln1_s + (size_t)(l + 1) * C_,
                                            ln1_b + (size_t)(l + 1) * C_);
        } else {
            ln_red_kernel<<<BT_ / 8, 256>>>(part, bpr + (size_t)l * C_, x, h,
                                            lnf_s, lnf_b);
        }
    }

    tgemm_kernel<<<gHEAD, 256, GEMM_SMEM>>>(h, Wp, nullptr, nullptr, out,
                                 BT_, V_, C_, C_, VP_, 0, 0);
}

// round 16
// speedup vs baseline: 1.1321x; 1.0097x over previous
#include <cuda_runtime.h>
#include <math.h>
#include <stdint.h>

// ---------------- problem constants ----------------
#define B_   2
#define T_   1024
#define C_   768
#define H_   12
#define D_   64
#define L_   12
#define FF_  3072
#define V_   50257
#define VP_  50304          // 393 * 128
#define BT_  (B_ * T_)      // 2048
#define C3_  (3 * C_)       // 2304
#define SK_  3              // split-K factor for N=768 GEMMs

// ---------------- device scratch ----------------
__device__ float g_x  [BT_ * C_];
__device__ float g_h  [BT_ * C_];
__device__ float g_qkv[BT_ * C3_];
__device__ float g_y  [BT_ * C_];
__device__ float g_ff [BT_ * FF_];
__device__ float g_part[SK_ * BT_ * C_];     // split-K partials
__device__ float g_Wp [C_ * VP_];            // padded + tf32-rounded Whead
__device__ float g_Wqkv_t[L_ * C_ * C3_];    // tf32-rounded weights
__device__ float g_Wo_t  [L_ * C_ * C_];
__device__ float g_Wfc_t [L_ * C_ * FF_];
__device__ float g_Wpr_t [L_ * FF_ * C_];
__device__ int   g_idx_is64;

// sizes (in float4 units) for the merged prep kernel
#define N4_QKV (L_ * C_ * C3_ / 4)
#define N4_WO  (L_ * C_ * C_ / 4)
#define N4_FC  (L_ * C_ * FF_ / 4)
#define N4_PR  (L_ * FF_ * C_ / 4)
#define N4_RND (N4_QKV + N4_WO + N4_FC + N4_PR)
#define N4_WP  (C_ * VP_ / 4)
#define N4_ALL (N4_RND + N4_WP)

// ---------------- tf32 helper ----------------
__device__ __forceinline__ uint32_t tf32_of(float x) {
    uint32_t u;
    asm("cvt.rna.tf32.f32 %0, %1;" : "=r"(u) : "f"(x));
    return u;
}
__device__ __forceinline__ float tf32_round(float x) {
    return __uint_as_float(tf32_of(x));
}

// ---------------- idx dtype detection ----------------
__global__ void detect_idx_kernel(const int* w) {
    __shared__ int found;
    if (threadIdx.x == 0) found = 0;
    __syncthreads();
    for (int i = threadIdx.x; i < BT_ / 2; i += blockDim.x)
        if (w[2 * i + 1] != 0) found = 1;
    __syncthreads();
    if (threadIdx.x == 0) g_idx_is64 = found ? 0 : 1;
}

// ---------------- merged weight prep: tf32-round 4 groups + pad/round Whead ------
__global__ void prep_weights_kernel(const float* __restrict__ Wqkv,
                                    const float* __restrict__ Wo,
                                    const float* __restrict__ Wfc,
                                    const float* __restrict__ Wpr,
                                    const float* __restrict__ Whead,
                                    float* __restrict__ Dqkv,
                                    float* __restrict__ Do_,
                                    float* __restrict__ Dfc,
                                    float* __restrict__ Dpr,
                                    float* __restrict__ Wp) {
    int i = blockIdx.x * blockDim.x + threadIdx.x;
    if (i >= N4_ALL) return;
    if (i < N4_RND) {
        const float4* src;
        float4* dst;
        int j = i;
        if (j < N4_QKV) {
            src = reinterpret_cast<const float4*>(Wqkv);
            dst = reinterpret_cast<float4*>(Dqkv);
        } else if ((j -= N4_QKV) < N4_WO) {
            src = reinterpret_cast<const float4*>(Wo);
            dst = reinterpret_cast<float4*>(Do_);
        } else if ((j -= N4_WO) < N4_FC) {
            src = reinterpret_cast<const float4*>(Wfc);
            dst = reinterpret_cast<float4*>(Dfc);
        } else {
            j -= N4_FC;
            src = reinterpret_cast<const float4*>(Wpr);
            dst = reinterpret_cast<float4*>(Dpr);
        }
        float4 v = src[j];
        v.x = tf32_round(v.x); v.y = tf32_round(v.y);
        v.z = tf32_round(v.z); v.w = tf32_round(v.w);
        dst[j] = v;
    } else {
        int j = i - N4_RND;              // float4 index into Wp
        int e0  = j * 4;
        int row = e0 / VP_;
        int col = e0 - row * VP_;
        float4 o;
        o.x = (col     < V_) ? tf32_round(Whead[(size_t)row * V_ + col    ]) : 0.f;
        o.y = (col + 1 < V_) ? tf32_round(Whead[(size_t)row * V_ + col + 1]) : 0.f;
        o.z = (col + 2 < V_) ? tf32_round(Whead[(size_t)row * V_ + col + 2]) : 0.f;
        o.w = (col + 3 < V_) ? tf32_round(Whead[(size_t)row * V_ + col + 3]) : 0.f;
        reinterpret_cast<float4*>(Wp)[j] = o;
    }
}

// ---------------- fused embedding + layer-0 LN: one warp per row ----------------
__global__ __launch_bounds__(256)
void embed_ln_kernel(const int* __restrict__ idxw, const float* __restrict__ tok,
                     const float* __restrict__ pos, float* __restrict__ x,
                     float* __restrict__ out, const float* __restrict__ s,
                     const float* __restrict__ b) {
    int warp = threadIdx.x >> 5;
    int lane = threadIdx.x & 31;
    int row  = blockIdx.x * 8 + warp;        // bt index
    int t    = row % T_;
    int token = g_idx_is64 ? idxw[2 * row] : idxw[row];
    const float* tr = tok + (size_t)token * C_;
    const float* pr = pos + (size_t)t * C_;
    float* xr = x + (size_t)row * C_;

    float4 v[6];
    float sum = 0.f, sq = 0.f;
#pragma unroll
    for (int i = 0; i < 6; i++) {
        int c = (i * 32 + lane) * 4;
        float4 tv = *reinterpret_cast<const float4*>(&tr[c]);
        float4 pv = *reinterpret_cast<const float4*>(&pr[c]);
        float4 nv;
        nv.x = tv.x + pv.x; nv.y = tv.y + pv.y;
        nv.z = tv.z + pv.z; nv.w = tv.w + pv.w;
        *reinterpret_cast<float4*>(&xr[c]) = nv;
        v[i] = nv;
        sum += nv.x + nv.y + nv.z + nv.w;
        sq  += nv.x * nv.x + nv.y * nv.y + nv.z * nv.z + nv.w * nv.w;
    }
#pragma unroll
    for (int off = 16; off > 0; off >>= 1) {
        sum += __shfl_xor_sync(0xffffffffu, sum, off);
        sq  += __shfl_xor_sync(0xffffffffu, sq,  off);
    }
    float mu  = sum * (1.f / C_);
    float var = sq * (1.f / C_) - mu * mu;
    float inv = rsqrtf(var + 1e-5f);
    float* orow = out + (size_t)row * C_;
#pragma unroll
    for (int i = 0; i < 6; i++) {
        int c = (i * 32 + lane) * 4;
        float4 sv = *reinterpret_cast<const float4*>(&s[c]);
        float4 bv = *reinterpret_cast<const float4*>(&b[c]);
        float4 o;
        o.x = tf32_round((v[i].x - mu) * inv * sv.x + bv.x);
        o.y = tf32_round((v[i].y - mu) * inv * sv.y + bv.y);
        o.z = tf32_round((v[i].z - mu) * inv * sv.z + bv.z);
        o.w = tf32_round((v[i].w - mu) * inv * sv.w + bv.w);
        *reinterpret_cast<float4*>(&orow[c]) = o;
    }
}

// ---------------- fused split-K reduce + residual + bias + layernorm ----------------
__global__ __launch_bounds__(256)
void ln_red_kernel(const float* __restrict__ part, const float* __restrict__ bias,
                   float* __restrict__ x, float* __restrict__ out,
                   const float* __restrict__ s, const float* __restrict__ b) {
    int warp = threadIdx.x >> 5;
    int lane = threadIdx.x & 31;
    int row  = blockIdx.x * 8 + warp;
    const size_t roff = (size_t)row * C_;
    const size_t MN   = (size_t)BT_ * C_;
    float* xr = x + roff;
    const float* p0 = part + roff;
    const float* p1 = part + MN + roff;
    const float* p2 = part + 2 * MN + roff;

    float4 v[6];
    float sum = 0.f, sq = 0.f;
#pragma unroll
    for (int i = 0; i < 6; i++) {
        int c = (i * 32 + lane) * 4;
        float4 xv = *reinterpret_cast<const float4*>(&xr[c]);
        float4 a0 = *reinterpret_cast<const float4*>(&p0[c]);
        float4 a1 = *reinterpret_cast<const float4*>(&p1[c]);
        float4 a2 = *reinterpret_cast<const float4*>(&p2[c]);
        float4 bv = *reinterpret_cast<const float4*>(&bias[c]);
        float4 nv;
        nv.x = xv.x + a0.x + a1.x + a2.x + bv.x;
        nv.y = xv.y + a0.y + a1.y + a2.y + bv.y;
        nv.z = xv.z + a0.z + a1.z + a2.z + bv.z;
        nv.w = xv.w + a0.w + a1.w + a2.w + bv.w;
        *reinterpret_cast<float4*>(&xr[c]) = nv;
        v[i] = nv;
        sum += nv.x + nv.y + nv.z + nv.w;
        sq  += nv.x * nv.x + nv.y * nv.y + nv.z * nv.z + nv.w * nv.w;
    }
#pragma unroll
    for (int off = 16; off > 0; off >>= 1) {
        sum += __shfl_xor_sync(0xffffffffu, sum, off);
        sq  += __shfl_xor_sync(0xffffffffu, sq,  off);
    }
    float mu  = sum * (1.f / C_);
    float var = sq * (1.f / C_) - mu * mu;
    float inv = rsqrtf(var + 1e-5f);
    float* orow = out + roff;
#pragma unroll
    for (int i = 0; i < 6; i++) {
        int c = (i * 32 + lane) * 4;
        float4 sv = *reinterpret_cast<const float4*>(&s[c]);
        float4 bv = *reinterpret_cast<const float4*>(&b[c]);
        float4 o;
        o.x = tf32_round((v[i].x - mu) * inv * sv.x + bv.x);
        o.y = tf32_round((v[i].y - mu) * inv * sv.y + bv.y);
        o.z = tf32_round((v[i].z - mu) * inv * sv.z + bv.z);
        o.w = tf32_round((v[i].w - mu) * inv * sv.w + bv.w);
        *reinterpret_cast<float4*>(&orow[c]) = o;
    }
}

// ---------------- layernorm (mid-layer ln2) ----------------
__global__ __launch_bounds__(256)
void ln_kernel(const float* __restrict__ x, float* __restrict__ out,
               const float* __restrict__ s, const float* __restrict__ b) {
    int warp = threadIdx.x >> 5;
    int lane = threadIdx.x & 31;
    int row  = blockIdx.x * 8 + warp;
    const float* xr = x + (size_t)row * C_;
    float4 v[6];
    float sum = 0.f, sq = 0.f;
#pragma unroll
    for (int i = 0; i < 6; i++) {
        v[i] = *reinterpret_cast<const float4*>(&xr[(i * 32 + lane) * 4]);
        sum += v[i].x + v[i].y + v[i].z + v[i].w;
        sq  += v[i].x * v[i].x + v[i].y * v[i].y
             + v[i].z * v[i].z + v[i].w * v[i].w;
    }
#pragma unroll
    for (int off = 16; off > 0; off >>= 1) {
        sum += __shfl_xor_sync(0xffffffffu, sum, off);
        sq  += __shfl_xor_sync(0xffffffffu, sq,  off);
    }
    float mu  = sum * (1.f / C_);
    float var = sq * (1.f / C_) - mu * mu;
    float inv = rsqrtf(var + 1e-5f);
    float* orow = out + (size_t)row * C_;
#pragma unroll
    for (int i = 0; i < 6; i++) {
        int c = (i * 32 + lane) * 4;
        float4 sv = *reinterpret_cast<const float4*>(&s[c]);
        float4 bv = *reinterpret_cast<const float4*>(&b[c]);
        float4 o;
        o.x = tf32_round((v[i].x - mu) * inv * sv.x + bv.x);
        o.y = tf32_round((v[i].y - mu) * inv * sv.y + bv.y);
        o.z = tf32_round((v[i].z - mu) * inv * sv.z + bv.z);
        o.w = tf32_round((v[i].w - mu) * inv * sv.w + bv.w);
        *reinterpret_cast<float4*>(&orow[c]) = o;
    }
}

// ---------------- cp.async helpers ----------------
__device__ __forceinline__ uint32_t smem_u32(const void* p) {
    return (uint32_t)__cvta_generic_to_shared(p);
}
__device__ __forceinline__ void cp16(uint32_t dst, const void* src) {
    asm volatile("cp.async.ca.shared.global [%0], [%1], 16;" :: "r"(dst), "l"(src));
}
__device__ __forceinline__ void cp_commit() {
    asm volatile("cp.async.commit_group;");
}
template <int Ngrp>
__device__ __forceinline__ void cp_wait() {
    asm volatile("cp.async.wait_group %0;" :: "n"(Ngrp));
}

__device__ __forceinline__ void mma_tf32(float* c, const uint32_t* a, const uint32_t* b) {
    asm volatile(
        "mma.sync.aligned.m16n8k8.row.col.f32.tf32.tf32.f32 "
        "{%0,%1,%2,%3}, {%4,%5,%6,%7}, {%8,%9}, {%0,%1,%2,%3};"
        : "+f"(c[0]), "+f"(c[1]), "+f"(c[2]), "+f"(c[3])
        : "r"(a[0]), "r"(a[1]), "r"(a[2]), "r"(a[3]), "r"(b[0]), "r"(b[1]));
}

// ---------------- tf32 GEMM: 128x128, BK=16, 3-stage cp.async (verified best) -----
#define GBM 128
#define GBN 128
#define GBK 16
#define ALD 20
#define BLD 136
#define A_ST (GBM * ALD)
#define B_ST (GBK * BLD)
#define GEMM_SMEM (3 * (A_ST + B_ST) * 4)

__global__ __launch_bounds__(256)
void tgemm_kernel(const float* __restrict__ A, const float* __restrict__ W,
                  const float* __restrict__ bias, const float* __restrict__ Res,
                  float* __restrict__ Cout, int M, int Nout, int K, int ldA,
                  int ldw, int act, int rnd) {
    extern __shared__ float smg[];
    float* sA = smg;
    float* sB = smg + 3 * A_ST;

    int z = blockIdx.z;
    const float* Ab = A + (size_t)z * K;
    const float* Wb = W + (size_t)z * K * ldw;

    int bn = blockIdx.x * GBN;
    int bm = blockIdx.y * GBM;
    int tid  = threadIdx.x;
    int lane = tid & 31;
    int warp = tid >> 5;
    int wm = warp >> 2;
    int wn = warp & 3;
    int g   = lane >> 2;
    int tig = lane & 3;

    int a_r  = tid >> 2;
    int a_f4 = (tid & 3) * 4;
    int b_r  = tid >> 5;
    int b_c4 = (tid & 31) * 4;

    auto load_tiles = [&](int s, int k0) {
        float* As = sA + s * A_ST;
        float* Bs = sB + s * B_ST;
#pragma unroll
        for (int it = 0; it < 2; it++) {
            int row = a_r + it * 64;
            cp16(smem_u32(&As[row * ALD + a_f4]),
                 &Ab[(size_t)(bm + row) * ldA + k0 + a_f4]);
        }
#pragma unroll
        for (int it = 0; it < 2; it++) {
            int kr = b_r + it * 8;
            cp16(smem_u32(&Bs[kr * BLD + b_c4]),
                 &Wb[(size_t)(k0 + kr) * ldw + bn + b_c4]);
        }
    };

    float acc[4][4][4];
#pragma unroll
    for (int mi = 0; mi < 4; mi++)
#pragma unroll
        for (int ni = 0; ni < 4; ni++)
#pragma unroll
            for (int e = 0; e < 4; e++) acc[mi][ni][e] = 0.f;

    int KT = K / GBK;
    load_tiles(0, 0);
    cp_commit();
    if (KT > 1) { load_tiles(1, GBK); cp_commit(); }

    for (int kt = 0; kt < KT; kt++) {
        if (kt + 1 < KT) cp_wait<1>(); else cp_wait<0>();
        __syncthreads();
        if (kt + 2 < KT) { load_tiles((kt + 2) % 3, (kt + 2) * GBK); cp_commit(); }

        const uint32_t* As = reinterpret_cast<const uint32_t*>(sA + (kt % 3) * A_ST);
        const uint32_t* Bs = reinterpret_cast<const uint32_t*>(sB + (kt % 3) * B_ST);
#pragma unroll
        for (int ks = 0; ks < 2; ks++) {
            int kb = ks * 8;
            uint32_t af[4][4], bf[4][2];
#pragma unroll
            for (int mi = 0; mi < 4; mi++) {
                int m0 = wm * 64 + mi * 16;
                af[mi][0] = As[(m0 + g    ) * ALD + kb + tig    ];
                af[mi][1] = As[(m0 + g + 8) * ALD + kb + tig    ];
                af[mi][2] = As[(m0 + g    ) * ALD + kb + tig + 4];
                af[mi][3] = As[(m0 + g + 8) * ALD + kb + tig + 4];
            }
#pragma unroll
            for (int ni = 0; ni < 4; ni++) {
                int n0 = wn * 32 + ni * 8;
                bf[ni][0] = Bs[(kb + tig    ) * BLD + n0 + g];
                bf[ni][1] = Bs[(kb + tig + 4) * BLD + n0 + g];
            }
#pragma unroll
            for (int mi = 0; mi < 4; mi++)
#pragma unroll
                for (int ni = 0; ni < 4; ni++)
                    mma_tf32(acc[mi][ni], af[mi], bf[ni]);
        }
    }
    __syncthreads();

    if (gridDim.z > 1) {
        float* P = Cout + (size_t)z * M * Nout;
#pragma unroll
        for (int mi = 0; mi < 4; mi++) {
            int r0 = bm + wm * 64 + mi * 16 + g;
#pragma unroll
            for (int ni = 0; ni < 4; ni++) {
                int col0 = bn + wn * 32 + ni * 8 + 2 * tig;
#pragma unroll
                for (int ep = 0; ep < 4; ep += 2) {
                    int row = r0 + (ep >> 1) * 8;
                    float2 st = {acc[mi][ni][ep], acc[mi][ni][ep + 1]};
                    *reinterpret_cast<float2*>(&P[(size_t)row * Nout + col0]) = st;
                }
            }
        }
        return;
    }

    bool evenN = ((Nout & 1) == 0);
#pragma unroll
    for (int mi = 0; mi < 4; mi++) {
        int r0 = bm + wm * 64 + mi * 16 + g;
#pragma unroll
        for (int ni = 0; ni < 4; ni++) {
            int col0 = bn + wn * 32 + ni * 8 + 2 * tig;
#pragma unroll
            for (int ep = 0; ep < 4; ep += 2) {
                int row = r0 + (ep >> 1) * 8;
                float v0 = acc[mi][ni][ep];
                float v1 = acc[mi][ni][ep + 1];
                if (bias) { v0 += bias[col0]; v1 += bias[col0 + 1]; }
                if (act == 1) {
                    v0 = 0.5f * v0 * (1.f + erff(v0 * 0.70710678118654752f));
                    v1 = 0.5f * v1 * (1.f + erff(v1 * 0.70710678118654752f));
                }
                if (rnd) { v0 = tf32_round(v0); v1 = tf32_round(v1); }
                size_t o = (size_t)row * Nout + col0;
                if (evenN) {
                    if (Res) { v0 += Res[o]; v1 += Res[o + 1]; }
                    float2 st = {v0, v1};
                    *reinterpret_cast<float2*>(&Cout[o]) = st;
                } else {
                    if (col0 < Nout) {
                        if (Res) v0 += Res[o];
                        Cout[o] = v0;
                    }
                    if (col0 + 1 < Nout) {
                        if (Res) v1 += Res[o + 1];
                        Cout[o + 1] = v1;
                    }
                }
            }
        }
    }
}

// ---------------- flash attention: one CTA per (b, h, 64-q tile) ----------------
#define ATT_SMEM ((3 * 64 * 64 + 64 * 65 + 128) * 4)

__global__ __launch_bounds__(256)
void attn_flash_kernel(const float* __restrict__ qkv, float* __restrict__ y) {
    extern __shared__ float sm[];
    float* Qs   = sm;
    float* Ks   = Qs + 64 * 64;
    float* Vs   = Ks + 64 * 64;
    float* Ps   = Vs + 64 * 64;
    float* mrow = Ps + 64 * 65;
    float* lrow = mrow + 64;

    int qt  = blockIdx.x;
    int h   = blockIdx.y;
    int b   = blockIdx.z;
    int tid = threadIdx.x;
    int tx  = tid & 15;
    int ty  = tid >> 4;
    const float scale = 0.125f;
    const float* base = qkv + (size_t)b * T_ * C3_;

    {
        int r  = tid >> 2;
        int d0 = (tid & 3) * 16;
        const float* qp = base + (size_t)(qt * 64 + r) * C3_ + h * 64 + d0;
#pragma unroll
        for (int i = 0; i < 4; i++) {
            float4 v = *reinterpret_cast<const float4*>(&qp[4 * i]);
            Qs[(d0 + 4 * i + 0) * 64 + r] = v.x;
            Qs[(d0 + 4 * i + 1) * 64 + r] = v.y;
            Qs[(d0 + 4 * i + 2) * 64 + r] = v.z;
            Qs[(d0 + 4 * i + 3) * 64 + r] = v.w;
        }
    }
    if (tid < 64) { mrow[tid] = -1e30f; lrow[tid] = 0.f; }

    float o[4][4];
#pragma unroll
    for (int i = 0; i < 4; i++)
#pragma unroll
        for (int j = 0; j < 4; j++) o[i][j] = 0.f;
    __syncthreads();

    for (int kt = 0; kt <= qt; kt++) {
        {
            int r  = tid >> 2;
            int d0 = (tid & 3) * 16;
            const float* kp = base + (size_t)(kt * 64 + r) * C3_ + C_ + h * 64 + d0;
            const float* vp = kp + C_;
#pragma unroll
            for (int i = 0; i < 4; i++) {
                float4 v = *reinterpret_cast<const float4*>(&kp[4 * i]);
                Ks[(d0 + 4 * i + 0) * 64 + r] = v.x;
                Ks[(d0 + 4 * i + 1) * 64 + r] = v.y;
                Ks[(d0 + 4 * i + 2) * 64 + r] = v.z;
                Ks[(d0 + 4 * i + 3) * 64 + r] = v.w;
            }
#pragma unroll
            for (int i = 0; i < 4; i++) {
                float4 v = *reinterpret_cast<const float4*>(&vp[4 * i]);
                *reinterpret_cast<float4*>(&Vs[r * 64 + d0 + 4 * i]) = v;
            }
        }
        __syncthreads();

        float cS[4][4];
#pragma unroll
        for (int i = 0; i < 4; i++)
#pragma unroll
            for (int j = 0; j < 4; j++) cS[i][j] = 0.f;
        for (int d = 0; d < 64; d++) {
            float4 aq = *reinterpret_cast<const float4*>(&Qs[d * 64 + 4 * ty]);
            float4 bk = *reinterpret_cast<const float4*>(&Ks[d * 64 + 4 * tx]);
            float a[4] = {aq.x, aq.y, aq.z, aq.w};
            float bb[4] = {bk.x, bk.y, bk.z, bk.w};
#pragma unroll
            for (int i = 0; i < 4; i++)
#pragma unroll
                for (int j = 0; j < 4; j++) cS[i][j] += a[i] * bb[j];
        }

        float al[4];
        bool diag = (kt == qt);
#pragma unroll
        for (int i = 0; i < 4; i++) {
            int r  = 4 * ty + i;
            int qg = qt * 64 + r;
            float rmax = -1e30f;
#pragma unroll
            for (int j = 0; j < 4; j++) {
                float s = cS[i][j] * scale;
                if (diag && (kt * 64 + 4 * tx + j) > qg) s = -1e30f;
                cS[i][j] = s;
                rmax = fmaxf(rmax, s);
            }
#pragma unroll
            for (int off = 8; off > 0; off >>= 1)
                rmax = fmaxf(rmax, __shfl_xor_sync(0xffffffffu, rmax, off));
            float mo = mrow[r];
            float mn = fmaxf(mo, rmax);
            float sum = 0.f;
#pragma unroll
            for (int j = 0; j < 4; j++) {
                float p = __expf(cS[i][j] - mn);
                cS[i][j] = p;
                sum += p;
            }
#pragma unroll
            for (int off = 8; off > 0; off >>= 1)
                sum += __shfl_xor_sync(0xffffffffu, sum, off);
            al[i] = __expf(mo - mn);
            if (tx == 0) {
                mrow[r] = mn;
                lrow[r] = lrow[r] * al[i] + sum;
            }
        }
#pragma unroll
        for (int i = 0; i < 4; i++) {
#pragma unroll
            for (int j = 0; j < 4; j++) {
                o[i][j] *= al[i];
                Ps[(4 * ty + i) * 65 + 4 * tx + j] = cS[i][j];
            }
        }
        __syncthreads();

        for (int k = 0; k < 64; k++) {
            float a0 = Ps[(4 * ty + 0) * 65 + k];
            float a1 = Ps[(4 * ty + 1) * 65 + k];
            float a2 = Ps[(4 * ty + 2) * 65 + k];
            float a3 = Ps[(4 * ty + 3) * 65 + k];
            float4 bv = *reinterpret_cast<const float4*>(&Vs[k * 64 + 4 * tx]);
            float bb[4] = {bv.x, bv.y, bv.z, bv.w};
#pragma unroll
            for (int j = 0; j < 4; j++) {
                o[0][j] += a0 * bb[j];
                o[1][j] += a1 * bb[j];
                o[2][j] += a2 * bb[j];
                o[3][j] += a3 * bb[j];
            }
        }
        __syncthreads();
    }

#pragma unroll
    for (int i = 0; i < 4; i++) {
        int r = 4 * ty + i;
        float linv = 1.f / lrow[r];
        size_t row = (size_t)(b * T_ + qt * 64 + r) * C_ + h * 64 + 4 * tx;
        float4 v;
        v.x = tf32_round(o[i][0] * linv); v.y = tf32_round(o[i][1] * linv);
        v.z = tf32_round(o[i][2] * linv); v.w = tf32_round(o[i][3] * linv);
        *reinterpret_cast<float4*>(&y[row]) = v;
    }
}

// ---------------- host launcher ----------------
extern "C" void kernel_launch(void* const* d_in, const int* in_sizes, int n_in,
                              void* d_out, int out_size) {
    const int*   idxw    = (const int*)  d_in[0];
    const float* tok_emb = (const float*)d_in[1];
    const float* pos_emb = (const float*)d_in[2];
    const float* ln1_s   = (const float*)d_in[3];
    const float* ln1_b   = (const float*)d_in[4];
    const float* Wqkv    = (const float*)d_in[5];
    const float* bqkv    = (const float*)d_in[6];
    const float* Wo      = (const float*)d_in[7];
    const float* bo      = (const float*)d_in[8];
    const float* ln2_s   = (const float*)d_in[9];
    const float* ln2_b   = (const float*)d_in[10];
    const float* Wfc     = (const float*)d_in[11];
    const float* bfc     = (const float*)d_in[12];
    const float* Wpr     = (const float*)d_in[13];
    const float* bpr     = (const float*)d_in[14];
    const float* lnf_s   = (const float*)d_in[15];
    const float* lnf_b   = (const float*)d_in[16];
    const float* Whead   = (const float*)d_in[17];
    float* out = (float*)d_out;

    float *x, *h, *qkv, *y, *ff, *part, *Wp, *Wqkv_t, *Wo_t, *Wfc_t, *Wpr_t;
    cudaGetSymbolAddress((void**)&x,      g_x);
    cudaGetSymbolAddress((void**)&h,      g_h);
    cudaGetSymbolAddress((void**)&qkv,    g_qkv);
    cudaGetSymbolAddress((void**)&y,      g_y);
    cudaGetSymbolAddress((void**)&ff,     g_ff);
    cudaGetSymbolAddress((void**)&part,   g_part);
    cudaGetSymbolAddress((void**)&Wp,     g_Wp);
    cudaGetSymbolAddress((void**)&Wqkv_t, g_Wqkv_t);
    cudaGetSymbolAddress((void**)&Wo_t,   g_Wo_t);
    cudaGetSymbolAddress((void**)&Wfc_t,  g_Wfc_t);
    cudaGetSymbolAddress((void**)&Wpr_t,  g_Wpr_t);

    cudaFuncSetAttribute(attn_flash_kernel,
                         cudaFuncAttributeMaxDynamicSharedMemorySize, ATT_SMEM);
    cudaFuncSetAttribute(tgemm_kernel,
                         cudaFuncAttributeMaxDynamicSharedMemorySize, GEMM_SMEM);

    // Launch order: detect(1), prep(2), embed_ln(3), tgemm-QKV(4) <- ncu samples #4
    detect_idx_kernel<<<1, 256>>>(idxw);
    prep_weights_kernel<<<(N4_ALL + 255) / 256, 256>>>(Wqkv, Wo, Wfc, Wpr, Whead,
                                                       Wqkv_t, Wo_t, Wfc_t, Wpr_t, Wp);
    embed_ln_kernel<<<BT_ / 8, 256>>>(idxw, tok_emb, pos_emb, x, h, ln1_s, ln1_b);

    dim3 gQKV(C3_ / GBN, BT_ / GBM);
    dim3 gPROJ_SK(C_ / GBN, BT_ / GBM, SK_);
    dim3 gFC(FF_ / GBN, BT_ / GBM);
    dim3 gHEAD(VP_ / GBN, BT_ / GBM);
    dim3 gATT(T_ / 64, H_, B_);

    for (int l = 0; l < L_; l++) {
        tgemm_kernel<<<gQKV, 256, GEMM_SMEM>>>(h, Wqkv_t + (size_t)l * C_ * C3_,
                                    bqkv + (size_t)l * C3_, nullptr, qkv,
                                    BT_, C3_, C_, C_, C3_, 0, 0);
        attn_flash_kernel<<<gATT, 256, ATT_SMEM>>>(qkv, y);
        tgemm_kernel<<<gPROJ_SK, 256, GEMM_SMEM>>>(y, Wo_t + (size_t)l * C_ * C_,
                                     nullptr, nullptr, part,
                                     BT_, C_, C_ / SK_, C_, C_, 0, 0);
        ln_red_kernel<<<BT_ / 8, 256>>>(part, bo + (size_t)l * C_, x, h,
                                        ln2_s + (size_t)l * C_, ln2_b + (size_t)l * C_);
        tgemm_kernel<<<gFC, 256, GEMM_SMEM>>>(h, Wfc_t + (size_t)l * C_ * FF_,
                                   bfc + (size_t)l * FF_, nullptr, ff,
                                   BT_, FF_, C_, C_, FF_, 1, 1);
        tgemm_kernel<<<gPROJ_SK, 256, GEMM_SMEM>>>(ff, Wpr_t + (size_t)l * FF_ * C_,
                                     nullptr, nullptr, part,
                                     BT_, C_, FF_ / SK_, FF_, C_, 0, 0);
        if (l + 1 < L_) {
            ln_red_kernel<<<BT_ / 8, 256>>>(part, bpr + (size_t)l * C_, x, h,
                                            ln1_s + (size_t)(l + 1) * C_,
                                            ln1_b + (size_t)(l + 1) * C_);
        } else {
            ln_red_kernel<<<BT_ / 8, 256>>>(part, bpr + (size_t)l * C_, x, h,
                                            lnf_s, lnf_b);
        }
    }

    tgemm_kernel<<<gHEAD, 256, GEMM_SMEM>>>(h, Wp, nullptr, nullptr, out,
                                 BT_, V_, C_, C_, VP_, 0, 0);
}